// round 11
// baseline (speedup 1.0000x reference)
#include <cuda_runtime.h>
#include <cuda_fp16.h>
#include <math.h>
#include <stdint.h>

// Problem constants
#define BATCH     1024
#define FDIM      1024
#define NCONCEPT  32768
#define INV_T     10.0f   // 1 / 0.1

#define TILE_B    16384          // one 128x64-fp16 swizzled tile (128 rows * 128 B)
#define KCHUNKS   16             // 1024 / 64
#define LO_SCALE  2048.0f        // 2^11

// sim pipeline: A (1 tile) + B (1 tile) per stage = 32 KB, 4 stages, 1 CTA/SM
#define STAGE_S   (2 * TILE_B)
#define NSTAGES_S 4
#define SMEM_SIM  (1024 + NSTAGES_S * STAGE_S)
// proj pipeline: Fhi, Flo, Whi, Wlo per stage = 64 KB, 3 stages
#define STAGE_P   (4 * TILE_B)
#define NSTAGES_P 3
#define SMEM_PROJ (1024 + NSTAGES_P * STAGE_P)
// softmax: full row staged in smem
#define SMEM_SOFT (NCONCEPT * 4)

// ---------------- scratch (device globals; no allocation allowed) ----------
__device__ float g_P[BATCH * FDIM];
__device__ float g_S[(size_t)BATCH * NCONCEPT];          // similarities (134 MB)
__device__ __align__(256) char g_Fh[(size_t)BATCH * FDIM * 2];
__device__ __align__(256) char g_Fl[(size_t)BATCH * FDIM * 2];
__device__ __align__(256) char g_Wh[(size_t)FDIM * FDIM * 2];
__device__ __align__(256) char g_Wl[(size_t)FDIM * FDIM * 2];
__device__ __align__(256) char g_Ah[(size_t)BATCH * FDIM * 2];
__device__ __align__(256) char g_Bh[(size_t)NCONCEPT * FDIM * 2];

// ---------------------------------------------------------------------------
// PTX helpers (baseline ISA only)
// ---------------------------------------------------------------------------
__device__ __forceinline__ uint32_t sm_u32(const void* p) {
    uint32_t a;
    asm("{ .reg .u64 t; cvta.to.shared.u64 t, %1; cvt.u32.u64 %0, t; }"
        : "=r"(a) : "l"(p));
    return a;
}

__device__ __forceinline__ void mbar_wait(uint32_t addr, int phase) {
    asm volatile(
        "{\n\t.reg .pred P;\n\t"
        "WL_%=:\n\t"
        "mbarrier.try_wait.parity.acquire.cta.shared::cta.b64 P, [%0], %1, 0x989680;\n\t"
        "@P bra.uni WD_%=;\n\t"
        "bra.uni WL_%=;\n\t"
        "WD_%=:\n\t}"
        :: "r"(addr), "r"((uint32_t)phase) : "memory");
}

#define MBAR_ARRIVE(addr) \
    asm volatile("mbarrier.arrive.shared.b64 _, [%0];" :: "r"(addr) : "memory")

#define LDSM4(R, addr) \
    asm volatile("ldmatrix.sync.aligned.m8n8.x4.shared.b16 {%0,%1,%2,%3}, [%4];" \
        : "=r"((R)[0]), "=r"((R)[1]), "=r"((R)[2]), "=r"((R)[3]) : "r"(addr))

#define MMA_F16_F32(C, A, b0_, b1_) \
    asm volatile("mma.sync.aligned.m16n8k16.row.col.f32.f16.f16.f32 " \
        "{%0,%1,%2,%3}, {%4,%5,%6,%7}, {%8,%9}, {%0,%1,%2,%3};" \
        : "+f"((C)[0]), "+f"((C)[1]), "+f"((C)[2]), "+f"((C)[3]) \
        : "r"((A)[0]), "r"((A)[1]), "r"((A)[2]), "r"((A)[3]), "r"(b0_), "r"(b1_))

#define MMA_F16_F16(C, A, b0_, b1_) \
    asm volatile("mma.sync.aligned.m16n8k16.row.col.f16.f16.f16.f16 " \
        "{%0,%1}, {%2,%3,%4,%5}, {%6,%7}, {%0,%1};" \
        : "+r"((C)[0]), "+r"((C)[1]) \
        : "r"((A)[0]), "r"((A)[1]), "r"((A)[2]), "r"((A)[3]), "r"(b0_), "r"(b1_))

#define BULK_LOAD(dst, src, bar) \
    asm volatile("cp.async.bulk.shared::cluster.global.mbarrier::complete_tx::bytes " \
        "[%0], [%1], %2, [%3];" \
        :: "r"(dst), "l"(src), "r"((uint32_t)TILE_B), "r"(bar) : "memory")

// ---------------------------------------------------------------------------
// fp32 -> fp16 two-limb split into pre-swizzled 128x64 tiles (no norm).
// ---------------------------------------------------------------------------
__global__ void __launch_bounds__(256)
convert_split2(const float4* __restrict__ src, char* __restrict__ hi, char* __restrict__ lo)
{
    const size_t i4 = (size_t)blockIdx.x * 256 + threadIdx.x;
    const int row = (int)(i4 >> 8);
    const int k   = ((int)i4 & 255) * 4;
    const float4 v = src[i4];
    const float x[4] = {v.x, v.y, v.z, v.w};

    unsigned short h[4], l[4];
#pragma unroll
    for (int j = 0; j < 4; ++j) {
        const __half hb = __float2half_rn(x[j]);
        const float r = (x[j] - __half2float(hb)) * LO_SCALE;
        h[j] = __half_as_ushort(hb);
        l[j] = __half_as_ushort(__float2half_rn(r));
    }

    const int tile = (row >> 7) * KCHUNKS + (k >> 6);
    uint32_t off = (uint32_t)((row & 127) * 128 + (k & 63) * 2);
    off ^= (off >> 3) & 0x70;

    uint2 ph, pl;
    ph.x = (uint32_t)h[0] | ((uint32_t)h[1] << 16);
    ph.y = (uint32_t)h[2] | ((uint32_t)h[3] << 16);
    pl.x = (uint32_t)l[0] | ((uint32_t)l[1] << 16);
    pl.y = (uint32_t)l[2] | ((uint32_t)l[3] << 16);
    *(uint2*)(hi + (size_t)tile * TILE_B + off) = ph;
    *(uint2*)(lo + (size_t)tile * TILE_B + off) = pl;
}

// ---------------------------------------------------------------------------
// A-side: fused L2-normalize + fp16 hi limb only. One CTA per row.
// ---------------------------------------------------------------------------
__global__ void __launch_bounds__(256)
convert_a(const float4* __restrict__ src, char* __restrict__ hi)
{
    const int row = blockIdx.x;
    const int tid = threadIdx.x;
    const float4 v = src[(size_t)row * 256 + tid];
    const float x[4] = {v.x, v.y, v.z, v.w};

    __shared__ float red[256];
    red[tid] = x[0]*x[0] + x[1]*x[1] + x[2]*x[2] + x[3]*x[3];
    __syncthreads();
#pragma unroll
    for (int off = 128; off > 0; off >>= 1) {
        if (tid < off) red[tid] += red[tid + off];
        __syncthreads();
    }
    const float inv = 1.0f / fmaxf(sqrtf(red[0]), 1e-12f);

    unsigned short h[4];
#pragma unroll
    for (int j = 0; j < 4; ++j)
        h[j] = __half_as_ushort(__float2half_rn(x[j] * inv));

    const int k = tid * 4;
    const int tile = (row >> 7) * KCHUNKS + (k >> 6);
    uint32_t off = (uint32_t)((row & 127) * 128 + (k & 63) * 2);
    off ^= (off >> 3) & 0x70;

    uint2 ph;
    ph.x = (uint32_t)h[0] | ((uint32_t)h[1] << 16);
    ph.y = (uint32_t)h[2] | ((uint32_t)h[3] << 16);
    *(uint2*)(hi + (size_t)tile * TILE_B + off) = ph;
}

// ---------------------------------------------------------------------------
// B-side: fp16 hi limb only, pre-swizzled tiles.
// ---------------------------------------------------------------------------
__global__ void __launch_bounds__(256)
convert_b(const float4* __restrict__ src, char* __restrict__ hi)
{
    const size_t i4 = (size_t)blockIdx.x * 256 + threadIdx.x;
    const int row = (int)(i4 >> 8);
    const int k   = ((int)i4 & 255) * 4;
    const float4 v = src[i4];
    const float x[4] = {v.x, v.y, v.z, v.w};

    unsigned short h[4];
#pragma unroll
    for (int j = 0; j < 4; ++j)
        h[j] = __half_as_ushort(__float2half_rn(x[j]));

    const int tile = (row >> 7) * KCHUNKS + (k >> 6);
    uint32_t off = (uint32_t)((row & 127) * 128 + (k & 63) * 2);
    off ^= (off >> 3) & 0x70;

    uint2 ph;
    ph.x = (uint32_t)h[0] | ((uint32_t)h[1] << 16);
    ph.y = (uint32_t)h[2] | ((uint32_t)h[3] << 16);
    *(uint2*)(hi + (size_t)tile * TILE_B + off) = ph;
}

// ---------------------------------------------------------------------------
// Projection GEMM, fp16 3-term limbs (~fp32). CTA 128x128, 16 warps.
// ---------------------------------------------------------------------------
__global__ void __launch_bounds__(512, 1)
proj_mma(const char* __restrict__ Fh, const char* __restrict__ Fl,
         const char* __restrict__ Wh, const char* __restrict__ Wl,
         const float* __restrict__ bias, float* __restrict__ P)
{
    extern __shared__ char smem_raw[];
    const uint32_t sbase = sm_u32(smem_raw);
    const uint32_t mbar0 = sbase;
    const uint32_t data0 = (sbase + 32u + 1023u) & ~1023u;

    const int tid = threadIdx.x;
    const int w = tid >> 5, l = tid & 31;
    const int wm = w & 3;
    const int wn = w >> 2;
    const int mb = blockIdx.x;
    const int nb = blockIdx.y;

    if (tid == 0) {
#pragma unroll
        for (int s = 0; s < NSTAGES_P; ++s)
            asm volatile("mbarrier.init.shared.b64 [%0], 1;" :: "r"(mbar0 + s * 8) : "memory");
    }
    __syncthreads();

    const int rowA  = wm * 32 + (l & 15);
    const uint32_t hA = (uint32_t)(l >> 4) << 4;
    const int rowB0 = wn * 32 + (l & 7) + ((l & 16) >> 1);
    const uint32_t hB = (uint32_t)(l & 8) << 1;
    const uint32_t swz = (uint32_t)(l & 7) << 4;

    float    acc[2][4][4];
    uint32_t accC[2][4][2];
#pragma unroll
    for (int i = 0; i < 2; ++i)
#pragma unroll
        for (int j = 0; j < 4; ++j) {
#pragma unroll
            for (int q = 0; q < 4; ++q) acc[i][j][q] = 0.f;
            accC[i][j][0] = 0u; accC[i][j][1] = 0u;
        }

    auto issue = [&](int kc, int s) {
        const uint32_t d = data0 + s * STAGE_P;
        const uint32_t bar = mbar0 + s * 8;
        const size_t aoff = ((size_t)mb * KCHUNKS + kc) * TILE_B;
        const size_t boff = ((size_t)nb * KCHUNKS + kc) * TILE_B;
        asm volatile("mbarrier.arrive.expect_tx.shared.b64 _, [%0], %1;"
                     :: "r"(bar), "r"((uint32_t)STAGE_P) : "memory");
        BULK_LOAD(d,              Fh + aoff, bar);
        BULK_LOAD(d + 1 * TILE_B, Fl + aoff, bar);
        BULK_LOAD(d + 2 * TILE_B, Wh + boff, bar);
        BULK_LOAD(d + 3 * TILE_B, Wl + boff, bar);
    };

    if (tid == 0) { issue(0, 0); issue(1, 1); }

    int ph[NSTAGES_P] = {0, 0, 0};

    for (int kc = 0; kc < KCHUNKS; ++kc) {
        const int s = kc % NSTAGES_P;
        mbar_wait(mbar0 + s * 8, ph[s]);
        ph[s] ^= 1;
        __syncthreads();
        if (tid == 0 && kc + 2 < KCHUNKS) issue(kc + 2, (kc + 2) % NSTAGES_P);

        const uint32_t aHb = data0 + s * STAGE_P;
        const uint32_t aLb = aHb + 1 * TILE_B;
        const uint32_t bHb = aHb + 2 * TILE_B;
        const uint32_t bLb = aHb + 3 * TILE_B;

#pragma unroll
        for (int ks = 0; ks < 4; ++ks) {
            uint32_t ah[2][4], al[2][4];
#pragma unroll
            for (int mi = 0; mi < 2; ++mi) {
                const uint32_t pa =
                    ((uint32_t)((rowA + mi * 16) * 128) + (uint32_t)(ks * 32) + hA) ^ swz;
                LDSM4(ah[mi], aHb + pa);
                LDSM4(al[mi], aLb + pa);
            }
#pragma unroll
            for (int nk = 0; nk < 2; ++nk) {
                const uint32_t pb =
                    ((uint32_t)((rowB0 + nk * 16) * 128) + (uint32_t)(ks * 32) + hB) ^ swz;
                uint32_t bh[4], bl[4];
                LDSM4(bh, bHb + pb);
                LDSM4(bl, bLb + pb);
#pragma unroll
                for (int mi = 0; mi < 2; ++mi) {
                    MMA_F16_F32(acc[mi][nk * 2 + 0], ah[mi], bh[0], bh[1]);
                    MMA_F16_F32(acc[mi][nk * 2 + 1], ah[mi], bh[2], bh[3]);
                    MMA_F16_F16(accC[mi][nk * 2 + 0], ah[mi], bl[0], bl[1]);
                    MMA_F16_F16(accC[mi][nk * 2 + 1], ah[mi], bl[2], bl[3]);
                    MMA_F16_F16(accC[mi][nk * 2 + 0], al[mi], bh[0], bh[1]);
                    MMA_F16_F16(accC[mi][nk * 2 + 1], al[mi], bh[2], bh[3]);
                }
            }
        }
    }

    const float cs = 1.0f / LO_SCALE;
    const int gm0 = mb * 128 + wm * 32 + (l >> 2);
    const int gn0 = nb * 128 + wn * 32 + (l & 3) * 2;
#pragma unroll
    for (int mi = 0; mi < 2; ++mi) {
#pragma unroll
        for (int nk = 0; nk < 2; ++nk) {
#pragma unroll
            for (int hf = 0; hf < 2; ++hf) {
                const int n = gn0 + nk * 16 + hf * 8;
                const float b0 = bias[n], b1 = bias[n + 1];
                const float* a = acc[mi][nk * 2 + hf];
                const uint32_t* c = accC[mi][nk * 2 + hf];
                const __half2 c0 = *(const __half2*)&c[0];
                const __half2 c1 = *(const __half2*)&c[1];
                float* p = P + (size_t)(gm0 + mi * 16) * FDIM + n;
                float2 v0, v1;
                v0.x = a[0] + __half2float(__low2half(c0))  * cs + b0;
                v0.y = a[1] + __half2float(__high2half(c0)) * cs + b1;
                v1.x = a[2] + __half2float(__low2half(c1))  * cs + b0;
                v1.y = a[3] + __half2float(__high2half(c1)) * cs + b1;
                *(float2*)p = v0;
                *(float2*)(p + (size_t)8 * FDIM) = v1;
            }
        }
    }
}

// ---------------------------------------------------------------------------
// Similarity GEMM: fp16 MMA with fp16 accumulation (2x issue rate vs f32),
// folded into fp32 shadow accumulators every 2 K-chunks.
// CTA 128x128, 8 warps (warp tile 64x32), 256 threads, 1 CTA/SM (no reg cap).
// Async full/cons mbarrier pipeline, 4 stages x 32 KB.
// ---------------------------------------------------------------------------
__global__ void __launch_bounds__(256, 1)
sim_mma(const char* __restrict__ Ah, const char* __restrict__ Bh,
        float* __restrict__ S)
{
    extern __shared__ char smem_raw[];
    const uint32_t sbase = sm_u32(smem_raw);
    const uint32_t full0 = sbase;            // 4 x 8B
    const uint32_t cons0 = sbase + 32;       // 4 x 8B
    const uint32_t data0 = (sbase + 64u + 1023u) & ~1023u;

    const int tid = threadIdx.x;
    const int w = tid >> 5, l = tid & 31;
    const int wm = w & 1;         // 0..1: M block of 64
    const int wn = w >> 1;        // 0..3: N block of 32
    const int mb = blockIdx.x;    // 0..7
    const int nb = blockIdx.y;    // 0..255

    if (tid == 0) {
#pragma unroll
        for (int s = 0; s < NSTAGES_S; ++s) {
            asm volatile("mbarrier.init.shared.b64 [%0], 1;"   :: "r"(full0 + s * 8) : "memory");
            asm volatile("mbarrier.init.shared.b64 [%0], 256;" :: "r"(cons0 + s * 8) : "memory");
        }
    }
    __syncthreads();

    const int rowA  = wm * 64 + (l & 15);
    const uint32_t hA = (uint32_t)(l >> 4) << 4;
    const int rowB0 = wn * 32 + (l & 7) + ((l & 16) >> 1);
    const uint32_t hB = (uint32_t)(l & 8) << 1;
    const uint32_t swz = (uint32_t)(l & 7) << 4;

    float    acc[4][4][4];    // fp32 shadow accumulators
    uint32_t accH[4][4][2];   // fp16x2 fast accumulators
#pragma unroll
    for (int i = 0; i < 4; ++i)
#pragma unroll
        for (int j = 0; j < 4; ++j) {
#pragma unroll
            for (int q = 0; q < 4; ++q) acc[i][j][q] = 0.f;
            accH[i][j][0] = 0u; accH[i][j][1] = 0u;
        }

    auto issue = [&](int kc, int s) {
        const uint32_t d = data0 + s * STAGE_S;
        const uint32_t bar = full0 + s * 8;
        const size_t aoff = ((size_t)mb * KCHUNKS + kc) * TILE_B;
        const size_t boff = ((size_t)nb * KCHUNKS + kc) * TILE_B;
        asm volatile("mbarrier.arrive.expect_tx.shared.b64 _, [%0], %1;"
                     :: "r"(bar), "r"((uint32_t)STAGE_S) : "memory");
        BULK_LOAD(d,          Ah + aoff, bar);
        BULK_LOAD(d + TILE_B, Bh + boff, bar);
    };

    if (tid == 0) { issue(0, 0); issue(1, 1); issue(2, 2); }

    int phf[NSTAGES_S] = {0, 0, 0, 0};
    int phc[NSTAGES_S] = {0, 0, 0, 0};   // used by tid 0 only

    for (int kc = 0; kc < KCHUNKS; ++kc) {
        const int s = kc & 3;
        mbar_wait(full0 + s * 8, phf[s]);
        phf[s] ^= 1;

        const uint32_t aHb = data0 + s * STAGE_S;
        const uint32_t bHb = aHb + TILE_B;

#pragma unroll
        for (int ks = 0; ks < 4; ++ks) {
            uint32_t ah[4][4];
#pragma unroll
            for (int mi = 0; mi < 4; ++mi) {
                const uint32_t pa =
                    ((uint32_t)((rowA + mi * 16) * 128) + (uint32_t)(ks * 32) + hA) ^ swz;
                LDSM4(ah[mi], aHb + pa);
            }
#pragma unroll
            for (int nk = 0; nk < 2; ++nk) {
                const uint32_t pb =
                    ((uint32_t)((rowB0 + nk * 16) * 128) + (uint32_t)(ks * 32) + hB) ^ swz;
                uint32_t bh[4];
                LDSM4(bh, bHb + pb);
#pragma unroll
                for (int mi = 0; mi < 4; ++mi) {
                    MMA_F16_F16(accH[mi][nk * 2 + 0], ah[mi], bh[0], bh[1]);
                    MMA_F16_F16(accH[mi][nk * 2 + 1], ah[mi], bh[2], bh[3]);
                }
            }
        }

        MBAR_ARRIVE(cons0 + s * 8);

        // fold fp16 partials into fp32 shadows every 2 chunks
        if (kc & 1) {
#pragma unroll
            for (int mi = 0; mi < 4; ++mi)
#pragma unroll
                for (int j = 0; j < 4; ++j) {
                    const float2 c0 = __half22float2(*(__half2*)&accH[mi][j][0]);
                    const float2 c1 = __half22float2(*(__half2*)&accH[mi][j][1]);
                    acc[mi][j][0] += c0.x; acc[mi][j][1] += c0.y;
                    acc[mi][j][2] += c1.x; acc[mi][j][3] += c1.y;
                    accH[mi][j][0] = 0u; accH[mi][j][1] = 0u;
                }
        }

        if (tid == 0 && kc + 3 < KCHUNKS) {
            const int s2 = (kc + 3) & 3;   // == (kc - 1) & 3: last used by chunk kc-1
            if (kc >= 1) {
                mbar_wait(cons0 + s2 * 8, phc[s2]);
                phc[s2] ^= 1;
            }
            issue(kc + 3, s2);
        }
    }

    const int gm0 = mb * 128 + wm * 64 + (l >> 2);
    const int gn0 = nb * 128 + wn * 32 + (l & 3) * 2;
#pragma unroll
    for (int mi = 0; mi < 4; ++mi) {
#pragma unroll
        for (int nk = 0; nk < 2; ++nk) {
#pragma unroll
            for (int hf = 0; hf < 2; ++hf) {
                const float* a = acc[mi][nk * 2 + hf];
                float* p = S + (size_t)(gm0 + mi * 16) * NCONCEPT + gn0 + nk * 16 + hf * 8;
                float2 v0, v1;
                v0.x = a[0]; v0.y = a[1];
                v1.x = a[2]; v1.y = a[3];
                *(float2*)p = v0;
                *(float2*)(p + (size_t)8 * NCONCEPT) = v1;
            }
        }
    }
}

// ---------------------------------------------------------------------------
// Per-row softmax(sim * INV_T) + argmax, row staged in SMEM (single S read).
// One CTA (512 threads) per row; 128 KB dynamic smem.
// ---------------------------------------------------------------------------
__global__ void __launch_bounds__(512)
softmax_row(const float* __restrict__ S,
            float* __restrict__ act,
            float* __restrict__ bidx)
{
    extern __shared__ float srow[];
    const int row = blockIdx.x;
    const int tid = threadIdx.x;
    const float4* s4 = (const float4*)(S + (size_t)row * NCONCEPT);
    float4* r4 = (float4*)srow;

    float m = -INFINITY;
    float Z = 0.f;
    int   bi = 0;

    for (int j = tid; j < NCONCEPT / 4; j += 512) {
        const float4 v = s4[j];
        r4[j] = v;
        const float x[4] = {v.x, v.y, v.z, v.w};
#pragma unroll
        for (int q = 0; q < 4; ++q) {
            if (x[q] > m) {
                Z = Z * __expf((m - x[q]) * INV_T) + 1.0f;
                m = x[q];
                bi = j * 4 + q;
            } else {
                Z += __expf((x[q] - m) * INV_T);
            }
        }
    }

    __shared__ float sm[512];
    __shared__ float sz[512];
    __shared__ int   si[512];
    sm[tid] = m; sz[tid] = Z; si[tid] = bi;
    __syncthreads();

#pragma unroll
    for (int off = 256; off > 0; off >>= 1) {
        if (tid < off) {
            const float m1 = sm[tid],       z1 = sz[tid];
            const float m2 = sm[tid + off], z2 = sz[tid + off];
            const int   i1 = si[tid],       i2 = si[tid + off];
            if (m2 > m1 || (m2 == m1 && i2 < i1)) {
                sm[tid] = m2;
                sz[tid] = z2 + z1 * __expf((m1 - m2) * INV_T);
                si[tid] = i2;
            } else {
                sz[tid] = z1 + z2 * __expf((m2 - m1) * INV_T);
            }
        }
        __syncthreads();
    }

    const float M    = sm[0];
    const float invZ = 1.0f / sz[0];
    float4* a4 = (float4*)(act + (size_t)row * NCONCEPT);
    for (int j = tid; j < NCONCEPT / 4; j += 512) {
        const float4 v = r4[j];
        float4 o;
        o.x = __expf((v.x - M) * INV_T) * invZ;
        o.y = __expf((v.y - M) * INV_T) * invZ;
        o.z = __expf((v.z - M) * INV_T) * invZ;
        o.w = __expf((v.w - M) * INV_T) * invZ;
        a4[j] = o;
    }

    if (tid == 0) bidx[row] = (float)si[0];
}

// ---------------------------------------------------------------------------
extern "C" void kernel_launch(void* const* d_in, const int* in_sizes, int n_in,
                              void* d_out, int out_size)
{
    const float* features   = (const float*)d_in[0];  // [1024, 1024]
    const float* W          = (const float*)d_in[1];  // [1024, 1024]
    const float* b          = (const float*)d_in[2];  // [1024]
    const float* prototypes = (const float*)d_in[3];  // [32768, 1024]

    float* out  = (float*)d_out;
    float* act  = out;                                   // [1024, 32768]
    float* bidx = out + (size_t)BATCH * NCONCEPT;        // [1024] as float

    float *pP = nullptr, *pS = nullptr;
    char *pFh = nullptr, *pFl = nullptr, *pWh = nullptr, *pWl = nullptr;
    char *pAh = nullptr, *pBh = nullptr;
    cudaGetSymbolAddress((void**)&pP,  g_P);
    cudaGetSymbolAddress((void**)&pS,  g_S);
    cudaGetSymbolAddress((void**)&pFh, g_Fh);
    cudaGetSymbolAddress((void**)&pFl, g_Fl);
    cudaGetSymbolAddress((void**)&pWh, g_Wh);
    cudaGetSymbolAddress((void**)&pWl, g_Wl);
    cudaGetSymbolAddress((void**)&pAh, g_Ah);
    cudaGetSymbolAddress((void**)&pBh, g_Bh);

    cudaFuncSetAttribute(proj_mma, cudaFuncAttributeMaxDynamicSharedMemorySize, SMEM_PROJ);
    cudaFuncSetAttribute(sim_mma,  cudaFuncAttributeMaxDynamicSharedMemorySize, SMEM_SIM);
    cudaFuncSetAttribute(softmax_row, cudaFuncAttributeMaxDynamicSharedMemorySize, SMEM_SOFT);

    // 1) split features and W into fp16 limbs (pre-swizzled tiles)
    convert_split2<<<(BATCH * FDIM / 4) / 256, 256>>>((const float4*)features, pFh, pFl);
    convert_split2<<<(FDIM * FDIM / 4) / 256, 256>>>((const float4*)W, pWh, pWl);

    // 2) projection via fp16 3-term mma: P = F @ W^T + b
    proj_mma<<<dim3(BATCH / 128, FDIM / 128), 512, SMEM_PROJ>>>(
        pFh, pFl, pWh, pWl, b, pP);

    // 3) A: fused L2-normalize + fp16 hi limb; B: fp16 hi limb
    convert_a<<<BATCH, 256>>>((const float4*)pP, pAh);
    convert_b<<<(NCONCEPT * FDIM / 4) / 256, 256>>>((const float4*)prototypes, pBh);

    // 4) similarities via fp16-accum mma.sync + periodic fp32 folding
    sim_mma<<<dim3(BATCH / 128, NCONCEPT / 128), 256, SMEM_SIM>>>(pAh, pBh, pS);

    // 5) per-row softmax(S/T) + argmax (smem-staged, single S read)
    softmax_row<<<BATCH, 512, SMEM_SOFT>>>(pS, act, bidx);
}

// round 12
// speedup vs baseline: 1.0717x; 1.0717x over previous
#include <cuda_runtime.h>
#include <cuda_fp16.h>
#include <math.h>
#include <stdint.h>

// Problem constants
#define BATCH     1024
#define FDIM      1024
#define NCONCEPT  32768
#define INV_T     10.0f   // 1 / 0.1

#define TILE_B    16384          // one 128x64-fp16 swizzled tile (128 rows * 128 B)
#define KCHUNKS   16             // 1024 / 64
#define LO_SCALE  2048.0f        // 2^11

// sim pipeline: A (1 tile) + B (2 tiles) per stage = 48 KB, 4 stages (async)
#define STAGE_S   (3 * TILE_B)
#define NSTAGES_S 4
#define SMEM_SIM  (1024 + NSTAGES_S * STAGE_S)
// proj pipeline: Fhi, Flo, Whi, Wlo per stage = 64 KB, 3 stages
#define STAGE_P   (4 * TILE_B)
#define NSTAGES_P 3
#define SMEM_PROJ (1024 + NSTAGES_P * STAGE_P)
// softmax: full row staged in smem
#define SMEM_SOFT (NCONCEPT * 4)

// ---------------- scratch (device globals; no allocation allowed) ----------
__device__ float g_P[BATCH * FDIM];
__device__ float g_S[(size_t)BATCH * NCONCEPT];          // similarities (134 MB)
__device__ __align__(256) char g_Fh[(size_t)BATCH * FDIM * 2];
__device__ __align__(256) char g_Fl[(size_t)BATCH * FDIM * 2];
__device__ __align__(256) char g_Wh[(size_t)FDIM * FDIM * 2];
__device__ __align__(256) char g_Wl[(size_t)FDIM * FDIM * 2];
__device__ __align__(256) char g_Ah[(size_t)BATCH * FDIM * 2];
__device__ __align__(256) char g_Bh[(size_t)NCONCEPT * FDIM * 2];

// ---------------------------------------------------------------------------
// PTX helpers (baseline ISA only)
// ---------------------------------------------------------------------------
__device__ __forceinline__ uint32_t sm_u32(const void* p) {
    uint32_t a;
    asm("{ .reg .u64 t; cvta.to.shared.u64 t, %1; cvt.u32.u64 %0, t; }"
        : "=r"(a) : "l"(p));
    return a;
}

__device__ __forceinline__ void mbar_wait(uint32_t addr, int phase) {
    asm volatile(
        "{\n\t.reg .pred P;\n\t"
        "WL_%=:\n\t"
        "mbarrier.try_wait.parity.acquire.cta.shared::cta.b64 P, [%0], %1, 0x989680;\n\t"
        "@P bra.uni WD_%=;\n\t"
        "bra.uni WL_%=;\n\t"
        "WD_%=:\n\t}"
        :: "r"(addr), "r"((uint32_t)phase) : "memory");
}

#define MBAR_ARRIVE(addr) \
    asm volatile("mbarrier.arrive.shared.b64 _, [%0];" :: "r"(addr) : "memory")

#define LDSM4(R, addr) \
    asm volatile("ldmatrix.sync.aligned.m8n8.x4.shared.b16 {%0,%1,%2,%3}, [%4];" \
        : "=r"((R)[0]), "=r"((R)[1]), "=r"((R)[2]), "=r"((R)[3]) : "r"(addr))

#define MMA_F16_F32(C, A, b0_, b1_) \
    asm volatile("mma.sync.aligned.m16n8k16.row.col.f32.f16.f16.f32 " \
        "{%0,%1,%2,%3}, {%4,%5,%6,%7}, {%8,%9}, {%0,%1,%2,%3};" \
        : "+f"((C)[0]), "+f"((C)[1]), "+f"((C)[2]), "+f"((C)[3]) \
        : "r"((A)[0]), "r"((A)[1]), "r"((A)[2]), "r"((A)[3]), "r"(b0_), "r"(b1_))

#define MMA_F16_F16(C, A, b0_, b1_) \
    asm volatile("mma.sync.aligned.m16n8k16.row.col.f16.f16.f16.f16 " \
        "{%0,%1}, {%2,%3,%4,%5}, {%6,%7}, {%0,%1};" \
        : "+r"((C)[0]), "+r"((C)[1]) \
        : "r"((A)[0]), "r"((A)[1]), "r"((A)[2]), "r"((A)[3]), "r"(b0_), "r"(b1_))

#define BULK_LOAD(dst, src, bar) \
    asm volatile("cp.async.bulk.shared::cluster.global.mbarrier::complete_tx::bytes " \
        "[%0], [%1], %2, [%3];" \
        :: "r"(dst), "l"(src), "r"((uint32_t)TILE_B), "r"(bar) : "memory")

// ---------------------------------------------------------------------------
// fp32 -> fp16 two-limb split into pre-swizzled 128x64 tiles (no norm).
// ---------------------------------------------------------------------------
__global__ void __launch_bounds__(256)
convert_split2(const float4* __restrict__ src, char* __restrict__ hi, char* __restrict__ lo)
{
    const size_t i4 = (size_t)blockIdx.x * 256 + threadIdx.x;
    const int row = (int)(i4 >> 8);
    const int k   = ((int)i4 & 255) * 4;
    const float4 v = src[i4];
    const float x[4] = {v.x, v.y, v.z, v.w};

    unsigned short h[4], l[4];
#pragma unroll
    for (int j = 0; j < 4; ++j) {
        const __half hb = __float2half_rn(x[j]);
        const float r = (x[j] - __half2float(hb)) * LO_SCALE;
        h[j] = __half_as_ushort(hb);
        l[j] = __half_as_ushort(__float2half_rn(r));
    }

    const int tile = (row >> 7) * KCHUNKS + (k >> 6);
    uint32_t off = (uint32_t)((row & 127) * 128 + (k & 63) * 2);
    off ^= (off >> 3) & 0x70;

    uint2 ph, pl;
    ph.x = (uint32_t)h[0] | ((uint32_t)h[1] << 16);
    ph.y = (uint32_t)h[2] | ((uint32_t)h[3] << 16);
    pl.x = (uint32_t)l[0] | ((uint32_t)l[1] << 16);
    pl.y = (uint32_t)l[2] | ((uint32_t)l[3] << 16);
    *(uint2*)(hi + (size_t)tile * TILE_B + off) = ph;
    *(uint2*)(lo + (size_t)tile * TILE_B + off) = pl;
}

// ---------------------------------------------------------------------------
// A-side: fused L2-normalize + fp16 hi limb only. One CTA per row.
// ---------------------------------------------------------------------------
__global__ void __launch_bounds__(256)
convert_a(const float4* __restrict__ src, char* __restrict__ hi)
{
    const int row = blockIdx.x;
    const int tid = threadIdx.x;
    const float4 v = src[(size_t)row * 256 + tid];
    const float x[4] = {v.x, v.y, v.z, v.w};

    __shared__ float red[256];
    red[tid] = x[0]*x[0] + x[1]*x[1] + x[2]*x[2] + x[3]*x[3];
    __syncthreads();
#pragma unroll
    for (int off = 128; off > 0; off >>= 1) {
        if (tid < off) red[tid] += red[tid + off];
        __syncthreads();
    }
    const float inv = 1.0f / fmaxf(sqrtf(red[0]), 1e-12f);

    unsigned short h[4];
#pragma unroll
    for (int j = 0; j < 4; ++j)
        h[j] = __half_as_ushort(__float2half_rn(x[j] * inv));

    const int k = tid * 4;
    const int tile = (row >> 7) * KCHUNKS + (k >> 6);
    uint32_t off = (uint32_t)((row & 127) * 128 + (k & 63) * 2);
    off ^= (off >> 3) & 0x70;

    uint2 ph;
    ph.x = (uint32_t)h[0] | ((uint32_t)h[1] << 16);
    ph.y = (uint32_t)h[2] | ((uint32_t)h[3] << 16);
    *(uint2*)(hi + (size_t)tile * TILE_B + off) = ph;
}

// ---------------------------------------------------------------------------
// B-side: fp16 hi limb only, pre-swizzled tiles.
// ---------------------------------------------------------------------------
__global__ void __launch_bounds__(256)
convert_b(const float4* __restrict__ src, char* __restrict__ hi)
{
    const size_t i4 = (size_t)blockIdx.x * 256 + threadIdx.x;
    const int row = (int)(i4 >> 8);
    const int k   = ((int)i4 & 255) * 4;
    const float4 v = src[i4];
    const float x[4] = {v.x, v.y, v.z, v.w};

    unsigned short h[4];
#pragma unroll
    for (int j = 0; j < 4; ++j)
        h[j] = __half_as_ushort(__float2half_rn(x[j]));

    const int tile = (row >> 7) * KCHUNKS + (k >> 6);
    uint32_t off = (uint32_t)((row & 127) * 128 + (k & 63) * 2);
    off ^= (off >> 3) & 0x70;

    uint2 ph;
    ph.x = (uint32_t)h[0] | ((uint32_t)h[1] << 16);
    ph.y = (uint32_t)h[2] | ((uint32_t)h[3] << 16);
    *(uint2*)(hi + (size_t)tile * TILE_B + off) = ph;
}

// ---------------------------------------------------------------------------
// Projection GEMM, fp16 3-term limbs (~fp32). CTA 128x128, 16 warps.
// ---------------------------------------------------------------------------
__global__ void __launch_bounds__(512, 1)
proj_mma(const char* __restrict__ Fh, const char* __restrict__ Fl,
         const char* __restrict__ Wh, const char* __restrict__ Wl,
         const float* __restrict__ bias, float* __restrict__ P)
{
    extern __shared__ char smem_raw[];
    const uint32_t sbase = sm_u32(smem_raw);
    const uint32_t mbar0 = sbase;
    const uint32_t data0 = (sbase + 32u + 1023u) & ~1023u;

    const int tid = threadIdx.x;
    const int w = tid >> 5, l = tid & 31;
    const int wm = w & 3;
    const int wn = w >> 2;
    const int mb = blockIdx.x;
    const int nb = blockIdx.y;

    if (tid == 0) {
#pragma unroll
        for (int s = 0; s < NSTAGES_P; ++s)
            asm volatile("mbarrier.init.shared.b64 [%0], 1;" :: "r"(mbar0 + s * 8) : "memory");
    }
    __syncthreads();

    const int rowA  = wm * 32 + (l & 15);
    const uint32_t hA = (uint32_t)(l >> 4) << 4;
    const int rowB0 = wn * 32 + (l & 7) + ((l & 16) >> 1);
    const uint32_t hB = (uint32_t)(l & 8) << 1;
    const uint32_t swz = (uint32_t)(l & 7) << 4;

    float    acc[2][4][4];
    uint32_t accC[2][4][2];
#pragma unroll
    for (int i = 0; i < 2; ++i)
#pragma unroll
        for (int j = 0; j < 4; ++j) {
#pragma unroll
            for (int q = 0; q < 4; ++q) acc[i][j][q] = 0.f;
            accC[i][j][0] = 0u; accC[i][j][1] = 0u;
        }

    auto issue = [&](int kc, int s) {
        const uint32_t d = data0 + s * STAGE_P;
        const uint32_t bar = mbar0 + s * 8;
        const size_t aoff = ((size_t)mb * KCHUNKS + kc) * TILE_B;
        const size_t boff = ((size_t)nb * KCHUNKS + kc) * TILE_B;
        asm volatile("mbarrier.arrive.expect_tx.shared.b64 _, [%0], %1;"
                     :: "r"(bar), "r"((uint32_t)STAGE_P) : "memory");
        BULK_LOAD(d,              Fh + aoff, bar);
        BULK_LOAD(d + 1 * TILE_B, Fl + aoff, bar);
        BULK_LOAD(d + 2 * TILE_B, Wh + boff, bar);
        BULK_LOAD(d + 3 * TILE_B, Wl + boff, bar);
    };

    if (tid == 0) { issue(0, 0); issue(1, 1); }

    int ph[NSTAGES_P] = {0, 0, 0};

    for (int kc = 0; kc < KCHUNKS; ++kc) {
        const int s = kc % NSTAGES_P;
        mbar_wait(mbar0 + s * 8, ph[s]);
        ph[s] ^= 1;
        __syncthreads();
        if (tid == 0 && kc + 2 < KCHUNKS) issue(kc + 2, (kc + 2) % NSTAGES_P);

        const uint32_t aHb = data0 + s * STAGE_P;
        const uint32_t aLb = aHb + 1 * TILE_B;
        const uint32_t bHb = aHb + 2 * TILE_B;
        const uint32_t bLb = aHb + 3 * TILE_B;

#pragma unroll
        for (int ks = 0; ks < 4; ++ks) {
            uint32_t ah[2][4], al[2][4];
#pragma unroll
            for (int mi = 0; mi < 2; ++mi) {
                const uint32_t pa =
                    ((uint32_t)((rowA + mi * 16) * 128) + (uint32_t)(ks * 32) + hA) ^ swz;
                LDSM4(ah[mi], aHb + pa);
                LDSM4(al[mi], aLb + pa);
            }
#pragma unroll
            for (int nk = 0; nk < 2; ++nk) {
                const uint32_t pb =
                    ((uint32_t)((rowB0 + nk * 16) * 128) + (uint32_t)(ks * 32) + hB) ^ swz;
                uint32_t bh[4], bl[4];
                LDSM4(bh, bHb + pb);
                LDSM4(bl, bLb + pb);
#pragma unroll
                for (int mi = 0; mi < 2; ++mi) {
                    MMA_F16_F32(acc[mi][nk * 2 + 0], ah[mi], bh[0], bh[1]);
                    MMA_F16_F32(acc[mi][nk * 2 + 1], ah[mi], bh[2], bh[3]);
                    MMA_F16_F16(accC[mi][nk * 2 + 0], ah[mi], bl[0], bl[1]);
                    MMA_F16_F16(accC[mi][nk * 2 + 1], ah[mi], bl[2], bl[3]);
                    MMA_F16_F16(accC[mi][nk * 2 + 0], al[mi], bh[0], bh[1]);
                    MMA_F16_F16(accC[mi][nk * 2 + 1], al[mi], bh[2], bh[3]);
                }
            }
        }
    }

    const float cs = 1.0f / LO_SCALE;
    const int gm0 = mb * 128 + wm * 32 + (l >> 2);
    const int gn0 = nb * 128 + wn * 32 + (l & 3) * 2;
#pragma unroll
    for (int mi = 0; mi < 2; ++mi) {
#pragma unroll
        for (int nk = 0; nk < 2; ++nk) {
#pragma unroll
            for (int hf = 0; hf < 2; ++hf) {
                const int n = gn0 + nk * 16 + hf * 8;
                const float b0 = bias[n], b1 = bias[n + 1];
                const float* a = acc[mi][nk * 2 + hf];
                const uint32_t* c = accC[mi][nk * 2 + hf];
                const __half2 c0 = *(const __half2*)&c[0];
                const __half2 c1 = *(const __half2*)&c[1];
                float* p = P + (size_t)(gm0 + mi * 16) * FDIM + n;
                float2 v0, v1;
                v0.x = a[0] + __half2float(__low2half(c0))  * cs + b0;
                v0.y = a[1] + __half2float(__high2half(c0)) * cs + b1;
                v1.x = a[2] + __half2float(__low2half(c1))  * cs + b0;
                v1.y = a[3] + __half2float(__high2half(c1)) * cs + b1;
                *(float2*)p = v0;
                *(float2*)(p + (size_t)8 * FDIM) = v1;
            }
        }
    }
}

// ---------------------------------------------------------------------------
// Similarity GEMM, hybrid accumulation (R9 shape + R5-proven MMA co-issue):
// CTA 128x256, 16 warps, warp tile 32x64. Per warp, N-cols nk 0-1 use
// f32-accum MMAs; nk 2-3 use f16-accum MMAs folded into f32 shadows every
// 2 K-chunks. Async full/cons mbarrier pipeline, 4 stages x 48 KB.
// ---------------------------------------------------------------------------
__global__ void __launch_bounds__(512, 1)
sim_mma(const char* __restrict__ Ah, const char* __restrict__ Bh,
        float* __restrict__ S)
{
    extern __shared__ char smem_raw[];
    const uint32_t sbase = sm_u32(smem_raw);
    const uint32_t full0 = sbase;            // 4 x 8B
    const uint32_t cons0 = sbase + 32;       // 4 x 8B
    const uint32_t data0 = (sbase + 64u + 1023u) & ~1023u;

    const int tid = threadIdx.x;
    const int w = tid >> 5, l = tid & 31;
    const int wm = w & 3;
    const int wn = w >> 2;
    const int mb = blockIdx.x;    // 0..7
    const int nb = blockIdx.y;    // 0..127

    if (tid == 0) {
#pragma unroll
        for (int s = 0; s < NSTAGES_S; ++s) {
            asm volatile("mbarrier.init.shared.b64 [%0], 1;"   :: "r"(full0 + s * 8) : "memory");
            asm volatile("mbarrier.init.shared.b64 [%0], 512;" :: "r"(cons0 + s * 8) : "memory");
        }
    }
    __syncthreads();

    const int rowA  = wm * 32 + (l & 15);
    const uint32_t hA = (uint32_t)(l >> 4) << 4;
    const int rowB0 = (wn & 1) * 64 + (l & 7) + ((l & 16) >> 1);
    const uint32_t hB = (uint32_t)(l & 8) << 1;
    const uint32_t swz = (uint32_t)(l & 7) << 4;
    const uint32_t bsel = (uint32_t)(wn >> 1) * TILE_B;

    float    acc32[2][4][4];   // nk 0-1: f32-accum
    float    accS [2][4][4];   // nk 2-3: f32 shadow for f16 partials
    uint32_t accH [2][4][2];   // nk 2-3: f16x2 fast accumulators
#pragma unroll
    for (int i = 0; i < 2; ++i)
#pragma unroll
        for (int j = 0; j < 4; ++j) {
#pragma unroll
            for (int q = 0; q < 4; ++q) { acc32[i][j][q] = 0.f; accS[i][j][q] = 0.f; }
            accH[i][j][0] = 0u; accH[i][j][1] = 0u;
        }

    auto issue = [&](int kc, int s) {
        const uint32_t d = data0 + s * STAGE_S;
        const uint32_t bar = full0 + s * 8;
        const size_t aoff  = ((size_t)mb * KCHUNKS + kc) * TILE_B;
        const size_t boff0 = ((size_t)(nb * 2 + 0) * KCHUNKS + kc) * TILE_B;
        const size_t boff1 = ((size_t)(nb * 2 + 1) * KCHUNKS + kc) * TILE_B;
        asm volatile("mbarrier.arrive.expect_tx.shared.b64 _, [%0], %1;"
                     :: "r"(bar), "r"((uint32_t)STAGE_S) : "memory");
        BULK_LOAD(d,              Ah + aoff,  bar);
        BULK_LOAD(d + 1 * TILE_B, Bh + boff0, bar);
        BULK_LOAD(d + 2 * TILE_B, Bh + boff1, bar);
    };

    if (tid == 0) { issue(0, 0); issue(1, 1); issue(2, 2); }

    int phf[NSTAGES_S] = {0, 0, 0, 0};
    int phc[NSTAGES_S] = {0, 0, 0, 0};   // used by tid 0 only

    for (int kc = 0; kc < KCHUNKS; ++kc) {
        const int s = kc & 3;
        mbar_wait(full0 + s * 8, phf[s]);
        phf[s] ^= 1;

        const uint32_t aHb = data0 + s * STAGE_S;
        const uint32_t bHb = aHb + TILE_B + bsel;

#pragma unroll
        for (int ks = 0; ks < 4; ++ks) {
            uint32_t ah[2][4];
#pragma unroll
            for (int mi = 0; mi < 2; ++mi) {
                const uint32_t pa =
                    ((uint32_t)((rowA + mi * 16) * 128) + (uint32_t)(ks * 32) + hA) ^ swz;
                LDSM4(ah[mi], aHb + pa);
            }
#pragma unroll
            for (int nk = 0; nk < 4; ++nk) {
                const uint32_t pb =
                    ((uint32_t)((rowB0 + nk * 16) * 128) + (uint32_t)(ks * 32) + hB) ^ swz;
                uint32_t bh[4];
                LDSM4(bh, bHb + pb);
                if (nk < 2) {
#pragma unroll
                    for (int mi = 0; mi < 2; ++mi) {
                        MMA_F16_F32(acc32[mi][nk * 2 + 0], ah[mi], bh[0], bh[1]);
                        MMA_F16_F32(acc32[mi][nk * 2 + 1], ah[mi], bh[2], bh[3]);
                    }
                } else {
#pragma unroll
                    for (int mi = 0; mi < 2; ++mi) {
                        MMA_F16_F16(accH[mi][(nk - 2) * 2 + 0], ah[mi], bh[0], bh[1]);
                        MMA_F16_F16(accH[mi][(nk - 2) * 2 + 1], ah[mi], bh[2], bh[3]);
                    }
                }
            }
        }

        MBAR_ARRIVE(cons0 + s * 8);

        // fold f16 partials into f32 shadows every 2 chunks
        if (kc & 1) {
#pragma unroll
            for (int mi = 0; mi < 2; ++mi)
#pragma unroll
                for (int j = 0; j < 4; ++j) {
                    const float2 c0 = __half22float2(*(__half2*)&accH[mi][j][0]);
                    const float2 c1 = __half22float2(*(__half2*)&accH[mi][j][1]);
                    accS[mi][j][0] += c0.x; accS[mi][j][1] += c0.y;
                    accS[mi][j][2] += c1.x; accS[mi][j][3] += c1.y;
                    accH[mi][j][0] = 0u; accH[mi][j][1] = 0u;
                }
        }

        if (tid == 0 && kc + 3 < KCHUNKS) {
            const int s2 = (kc + 3) & 3;   // stage last used by chunk kc-1
            if (kc >= 1) {
                mbar_wait(cons0 + s2 * 8, phc[s2]);
                phc[s2] ^= 1;
            }
            issue(kc + 3, s2);
        }
    }

    const int gm0 = mb * 128 + wm * 32 + (l >> 2);
    const int gn0 = nb * 256 + wn * 64 + (l & 3) * 2;
#pragma unroll
    for (int mi = 0; mi < 2; ++mi) {
#pragma unroll
        for (int nk = 0; nk < 4; ++nk) {
#pragma unroll
            for (int hf = 0; hf < 2; ++hf) {
                const float* a = (nk < 2) ? acc32[mi][nk * 2 + hf]
                                          : accS[mi][(nk - 2) * 2 + hf];
                float* p = S + (size_t)(gm0 + mi * 16) * NCONCEPT + gn0 + nk * 16 + hf * 8;
                float2 v0, v1;
                v0.x = a[0]; v0.y = a[1];
                v1.x = a[2]; v1.y = a[3];
                *(float2*)p = v0;
                *(float2*)(p + (size_t)8 * NCONCEPT) = v1;
            }
        }
    }
}

// ---------------------------------------------------------------------------
// Per-row softmax(sim * INV_T) + argmax, row staged in SMEM (single S read).
// One CTA (512 threads) per row; 128 KB dynamic smem.
// ---------------------------------------------------------------------------
__global__ void __launch_bounds__(512)
softmax_row(const float* __restrict__ S,
            float* __restrict__ act,
            float* __restrict__ bidx)
{
    extern __shared__ float srow[];
    const int row = blockIdx.x;
    const int tid = threadIdx.x;
    const float4* s4 = (const float4*)(S + (size_t)row * NCONCEPT);
    float4* r4 = (float4*)srow;

    float m = -INFINITY;
    float Z = 0.f;
    int   bi = 0;

    for (int j = tid; j < NCONCEPT / 4; j += 512) {
        const float4 v = s4[j];
        r4[j] = v;
        const float x[4] = {v.x, v.y, v.z, v.w};
#pragma unroll
        for (int q = 0; q < 4; ++q) {
            if (x[q] > m) {
                Z = Z * __expf((m - x[q]) * INV_T) + 1.0f;
                m = x[q];
                bi = j * 4 + q;
            } else {
                Z += __expf((x[q] - m) * INV_T);
            }
        }
    }

    __shared__ float sm[512];
    __shared__ float sz[512];
    __shared__ int   si[512];
    sm[tid] = m; sz[tid] = Z; si[tid] = bi;
    __syncthreads();

#pragma unroll
    for (int off = 256; off > 0; off >>= 1) {
        if (tid < off) {
            const float m1 = sm[tid],       z1 = sz[tid];
            const float m2 = sm[tid + off], z2 = sz[tid + off];
            const int   i1 = si[tid],       i2 = si[tid + off];
            if (m2 > m1 || (m2 == m1 && i2 < i1)) {
                sm[tid] = m2;
                sz[tid] = z2 + z1 * __expf((m1 - m2) * INV_T);
                si[tid] = i2;
            } else {
                sz[tid] = z1 + z2 * __expf((m2 - m1) * INV_T);
            }
        }
        __syncthreads();
    }

    const float M    = sm[0];
    const float invZ = 1.0f / sz[0];
    float4* a4 = (float4*)(act + (size_t)row * NCONCEPT);
    for (int j = tid; j < NCONCEPT / 4; j += 512) {
        const float4 v = r4[j];
        float4 o;
        o.x = __expf((v.x - M) * INV_T) * invZ;
        o.y = __expf((v.y - M) * INV_T) * invZ;
        o.z = __expf((v.z - M) * INV_T) * invZ;
        o.w = __expf((v.w - M) * INV_T) * invZ;
        a4[j] = o;
    }

    if (tid == 0) bidx[row] = (float)si[0];
}

// ---------------------------------------------------------------------------
extern "C" void kernel_launch(void* const* d_in, const int* in_sizes, int n_in,
                              void* d_out, int out_size)
{
    const float* features   = (const float*)d_in[0];  // [1024, 1024]
    const float* W          = (const float*)d_in[1];  // [1024, 1024]
    const float* b          = (const float*)d_in[2];  // [1024]
    const float* prototypes = (const float*)d_in[3];  // [32768, 1024]

    float* out  = (float*)d_out;
    float* act  = out;                                   // [1024, 32768]
    float* bidx = out + (size_t)BATCH * NCONCEPT;        // [1024] as float

    float *pP = nullptr, *pS = nullptr;
    char *pFh = nullptr, *pFl = nullptr, *pWh = nullptr, *pWl = nullptr;
    char *pAh = nullptr, *pBh = nullptr;
    cudaGetSymbolAddress((void**)&pP,  g_P);
    cudaGetSymbolAddress((void**)&pS,  g_S);
    cudaGetSymbolAddress((void**)&pFh, g_Fh);
    cudaGetSymbolAddress((void**)&pFl, g_Fl);
    cudaGetSymbolAddress((void**)&pWh, g_Wh);
    cudaGetSymbolAddress((void**)&pWl, g_Wl);
    cudaGetSymbolAddress((void**)&pAh, g_Ah);
    cudaGetSymbolAddress((void**)&pBh, g_Bh);

    cudaFuncSetAttribute(proj_mma, cudaFuncAttributeMaxDynamicSharedMemorySize, SMEM_PROJ);
    cudaFuncSetAttribute(sim_mma,  cudaFuncAttributeMaxDynamicSharedMemorySize, SMEM_SIM);
    cudaFuncSetAttribute(softmax_row, cudaFuncAttributeMaxDynamicSharedMemorySize, SMEM_SOFT);

    // 1) split features and W into fp16 limbs (pre-swizzled tiles)
    convert_split2<<<(BATCH * FDIM / 4) / 256, 256>>>((const float4*)features, pFh, pFl);
    convert_split2<<<(FDIM * FDIM / 4) / 256, 256>>>((const float4*)W, pWh, pWl);

    // 2) projection via fp16 3-term mma: P = F @ W^T + b
    proj_mma<<<dim3(BATCH / 128, FDIM / 128), 512, SMEM_PROJ>>>(
        pFh, pFl, pWh, pWl, b, pP);

    // 3) A: fused L2-normalize + fp16 hi limb; B: fp16 hi limb
    convert_a<<<BATCH, 256>>>((const float4*)pP, pAh);
    convert_b<<<(NCONCEPT * FDIM / 4) / 256, 256>>>((const float4*)prototypes, pBh);

    // 4) similarities via hybrid f32/f16-accum mma.sync (co-issued kinds)
    sim_mma<<<dim3(BATCH / 128, NCONCEPT / 256), 512, SMEM_SIM>>>(pAh, pBh, pS);

    // 5) per-row softmax(S/T) + argmax (smem-staged, single S read)
    softmax_row<<<BATCH, 512, SMEM_SOFT>>>(pS, act, bidx);
}

// round 13
// speedup vs baseline: 1.1170x; 1.0422x over previous
#include <cuda_runtime.h>
#include <cuda_fp16.h>
#include <math.h>
#include <stdint.h>

// Problem constants
#define BATCH     1024
#define FDIM      1024
#define NCONCEPT  32768
#define INV_T     10.0f   // 1 / 0.1

#define TILE_B    16384          // one 128x64-fp16 swizzled tile (128 rows * 128 B)
#define KCHUNKS   16             // 1024 / 64
#define LO_SCALE  2048.0f        // 2^11

// sim pipeline: A (1 tile) + B (2 tiles) per stage = 48 KB, 4 stages (async)
#define STAGE_S   (3 * TILE_B)
#define NSTAGES_S 4
#define SMEM_SIM  (1024 + NSTAGES_S * STAGE_S)
// proj pipeline: Fhi, Flo, Whi, Wlo per stage = 64 KB, 3 stages
#define STAGE_P   (4 * TILE_B)
#define NSTAGES_P 3
#define SMEM_PROJ (1024 + NSTAGES_P * STAGE_P)
// softmax: full row staged in smem
#define SMEM_SOFT (NCONCEPT * 4)

// ---------------- scratch (device globals; no allocation allowed) ----------
__device__ float g_P[BATCH * FDIM];
__device__ float g_S[(size_t)BATCH * NCONCEPT];          // similarities (134 MB)
__device__ __align__(256) char g_Fh[(size_t)BATCH * FDIM * 2];
__device__ __align__(256) char g_Fl[(size_t)BATCH * FDIM * 2];
__device__ __align__(256) char g_Wh[(size_t)FDIM * FDIM * 2];
__device__ __align__(256) char g_Wl[(size_t)FDIM * FDIM * 2];
__device__ __align__(256) char g_Ah[(size_t)BATCH * FDIM * 2];
__device__ __align__(256) char g_Bh[(size_t)NCONCEPT * FDIM * 2];

// ---------------------------------------------------------------------------
// PTX helpers (baseline ISA only)
// ---------------------------------------------------------------------------
__device__ __forceinline__ uint32_t sm_u32(const void* p) {
    uint32_t a;
    asm("{ .reg .u64 t; cvta.to.shared.u64 t, %1; cvt.u32.u64 %0, t; }"
        : "=r"(a) : "l"(p));
    return a;
}

__device__ __forceinline__ void mbar_wait(uint32_t addr, int phase) {
    asm volatile(
        "{\n\t.reg .pred P;\n\t"
        "WL_%=:\n\t"
        "mbarrier.try_wait.parity.acquire.cta.shared::cta.b64 P, [%0], %1, 0x989680;\n\t"
        "@P bra.uni WD_%=;\n\t"
        "bra.uni WL_%=;\n\t"
        "WD_%=:\n\t}"
        :: "r"(addr), "r"((uint32_t)phase) : "memory");
}

#define MBAR_ARRIVE(addr) \
    asm volatile("mbarrier.arrive.shared.b64 _, [%0];" :: "r"(addr) : "memory")

#define LDSM4(R, addr) \
    asm volatile("ldmatrix.sync.aligned.m8n8.x4.shared.b16 {%0,%1,%2,%3}, [%4];" \
        : "=r"((R)[0]), "=r"((R)[1]), "=r"((R)[2]), "=r"((R)[3]) : "r"(addr))

#define MMA_F16_F32(C, A, b0_, b1_) \
    asm volatile("mma.sync.aligned.m16n8k16.row.col.f32.f16.f16.f32 " \
        "{%0,%1,%2,%3}, {%4,%5,%6,%7}, {%8,%9}, {%0,%1,%2,%3};" \
        : "+f"((C)[0]), "+f"((C)[1]), "+f"((C)[2]), "+f"((C)[3]) \
        : "r"((A)[0]), "r"((A)[1]), "r"((A)[2]), "r"((A)[3]), "r"(b0_), "r"(b1_))

#define MMA_F16_F16(C, A, b0_, b1_) \
    asm volatile("mma.sync.aligned.m16n8k16.row.col.f16.f16.f16.f16 " \
        "{%0,%1}, {%2,%3,%4,%5}, {%6,%7}, {%0,%1};" \
        : "+r"((C)[0]), "+r"((C)[1]) \
        : "r"((A)[0]), "r"((A)[1]), "r"((A)[2]), "r"((A)[3]), "r"(b0_), "r"(b1_))

#define BULK_LOAD(dst, src, bar) \
    asm volatile("cp.async.bulk.shared::cluster.global.mbarrier::complete_tx::bytes " \
        "[%0], [%1], %2, [%3];" \
        :: "r"(dst), "l"(src), "r"((uint32_t)TILE_B), "r"(bar) : "memory")

// ---------------------------------------------------------------------------
// fp32 -> fp16 two-limb split into pre-swizzled 128x64 tiles (no norm).
// ---------------------------------------------------------------------------
__global__ void __launch_bounds__(256)
convert_split2(const float4* __restrict__ src, char* __restrict__ hi, char* __restrict__ lo)
{
    const size_t i4 = (size_t)blockIdx.x * 256 + threadIdx.x;
    const int row = (int)(i4 >> 8);
    const int k   = ((int)i4 & 255) * 4;
    const float4 v = src[i4];
    const float x[4] = {v.x, v.y, v.z, v.w};

    unsigned short h[4], l[4];
#pragma unroll
    for (int j = 0; j < 4; ++j) {
        const __half hb = __float2half_rn(x[j]);
        const float r = (x[j] - __half2float(hb)) * LO_SCALE;
        h[j] = __half_as_ushort(hb);
        l[j] = __half_as_ushort(__float2half_rn(r));
    }

    const int tile = (row >> 7) * KCHUNKS + (k >> 6);
    uint32_t off = (uint32_t)((row & 127) * 128 + (k & 63) * 2);
    off ^= (off >> 3) & 0x70;

    uint2 ph, pl;
    ph.x = (uint32_t)h[0] | ((uint32_t)h[1] << 16);
    ph.y = (uint32_t)h[2] | ((uint32_t)h[3] << 16);
    pl.x = (uint32_t)l[0] | ((uint32_t)l[1] << 16);
    pl.y = (uint32_t)l[2] | ((uint32_t)l[3] << 16);
    *(uint2*)(hi + (size_t)tile * TILE_B + off) = ph;
    *(uint2*)(lo + (size_t)tile * TILE_B + off) = pl;
}

// ---------------------------------------------------------------------------
// A-side: fused L2-normalize + fp16 hi limb only. One CTA per row.
// ---------------------------------------------------------------------------
__global__ void __launch_bounds__(256)
convert_a(const float4* __restrict__ src, char* __restrict__ hi)
{
    const int row = blockIdx.x;
    const int tid = threadIdx.x;
    const float4 v = src[(size_t)row * 256 + tid];
    const float x[4] = {v.x, v.y, v.z, v.w};

    __shared__ float red[256];
    red[tid] = x[0]*x[0] + x[1]*x[1] + x[2]*x[2] + x[3]*x[3];
    __syncthreads();
#pragma unroll
    for (int off = 128; off > 0; off >>= 1) {
        if (tid < off) red[tid] += red[tid + off];
        __syncthreads();
    }
    const float inv = 1.0f / fmaxf(sqrtf(red[0]), 1e-12f);

    unsigned short h[4];
#pragma unroll
    for (int j = 0; j < 4; ++j)
        h[j] = __half_as_ushort(__float2half_rn(x[j] * inv));

    const int k = tid * 4;
    const int tile = (row >> 7) * KCHUNKS + (k >> 6);
    uint32_t off = (uint32_t)((row & 127) * 128 + (k & 63) * 2);
    off ^= (off >> 3) & 0x70;

    uint2 ph;
    ph.x = (uint32_t)h[0] | ((uint32_t)h[1] << 16);
    ph.y = (uint32_t)h[2] | ((uint32_t)h[3] << 16);
    *(uint2*)(hi + (size_t)tile * TILE_B + off) = ph;
}

// ---------------------------------------------------------------------------
// B-side: fp16 hi limb only, pre-swizzled tiles.
// ---------------------------------------------------------------------------
__global__ void __launch_bounds__(256)
convert_b(const float4* __restrict__ src, char* __restrict__ hi)
{
    const size_t i4 = (size_t)blockIdx.x * 256 + threadIdx.x;
    const int row = (int)(i4 >> 8);
    const int k   = ((int)i4 & 255) * 4;
    const float4 v = src[i4];
    const float x[4] = {v.x, v.y, v.z, v.w};

    unsigned short h[4];
#pragma unroll
    for (int j = 0; j < 4; ++j)
        h[j] = __half_as_ushort(__float2half_rn(x[j]));

    const int tile = (row >> 7) * KCHUNKS + (k >> 6);
    uint32_t off = (uint32_t)((row & 127) * 128 + (k & 63) * 2);
    off ^= (off >> 3) & 0x70;

    uint2 ph;
    ph.x = (uint32_t)h[0] | ((uint32_t)h[1] << 16);
    ph.y = (uint32_t)h[2] | ((uint32_t)h[3] << 16);
    *(uint2*)(hi + (size_t)tile * TILE_B + off) = ph;
}

// ---------------------------------------------------------------------------
// Projection GEMM, fp16 3-term limbs (~fp32). CTA 128x128, 16 warps.
// ---------------------------------------------------------------------------
__global__ void __launch_bounds__(512, 1)
proj_mma(const char* __restrict__ Fh, const char* __restrict__ Fl,
         const char* __restrict__ Wh, const char* __restrict__ Wl,
         const float* __restrict__ bias, float* __restrict__ P)
{
    extern __shared__ char smem_raw[];
    const uint32_t sbase = sm_u32(smem_raw);
    const uint32_t mbar0 = sbase;
    const uint32_t data0 = (sbase + 32u + 1023u) & ~1023u;

    const int tid = threadIdx.x;
    const int w = tid >> 5, l = tid & 31;
    const int wm = w & 3;
    const int wn = w >> 2;
    const int mb = blockIdx.x;
    const int nb = blockIdx.y;

    if (tid == 0) {
#pragma unroll
        for (int s = 0; s < NSTAGES_P; ++s)
            asm volatile("mbarrier.init.shared.b64 [%0], 1;" :: "r"(mbar0 + s * 8) : "memory");
    }
    __syncthreads();

    const int rowA  = wm * 32 + (l & 15);
    const uint32_t hA = (uint32_t)(l >> 4) << 4;
    const int rowB0 = wn * 32 + (l & 7) + ((l & 16) >> 1);
    const uint32_t hB = (uint32_t)(l & 8) << 1;
    const uint32_t swz = (uint32_t)(l & 7) << 4;

    float    acc[2][4][4];
    uint32_t accC[2][4][2];
#pragma unroll
    for (int i = 0; i < 2; ++i)
#pragma unroll
        for (int j = 0; j < 4; ++j) {
#pragma unroll
            for (int q = 0; q < 4; ++q) acc[i][j][q] = 0.f;
            accC[i][j][0] = 0u; accC[i][j][1] = 0u;
        }

    auto issue = [&](int kc, int s) {
        const uint32_t d = data0 + s * STAGE_P;
        const uint32_t bar = mbar0 + s * 8;
        const size_t aoff = ((size_t)mb * KCHUNKS + kc) * TILE_B;
        const size_t boff = ((size_t)nb * KCHUNKS + kc) * TILE_B;
        asm volatile("mbarrier.arrive.expect_tx.shared.b64 _, [%0], %1;"
                     :: "r"(bar), "r"((uint32_t)STAGE_P) : "memory");
        BULK_LOAD(d,              Fh + aoff, bar);
        BULK_LOAD(d + 1 * TILE_B, Fl + aoff, bar);
        BULK_LOAD(d + 2 * TILE_B, Wh + boff, bar);
        BULK_LOAD(d + 3 * TILE_B, Wl + boff, bar);
    };

    if (tid == 0) { issue(0, 0); issue(1, 1); }

    int ph[NSTAGES_P] = {0, 0, 0};

    for (int kc = 0; kc < KCHUNKS; ++kc) {
        const int s = kc % NSTAGES_P;
        mbar_wait(mbar0 + s * 8, ph[s]);
        ph[s] ^= 1;
        __syncthreads();
        if (tid == 0 && kc + 2 < KCHUNKS) issue(kc + 2, (kc + 2) % NSTAGES_P);

        const uint32_t aHb = data0 + s * STAGE_P;
        const uint32_t aLb = aHb + 1 * TILE_B;
        const uint32_t bHb = aHb + 2 * TILE_B;
        const uint32_t bLb = aHb + 3 * TILE_B;

#pragma unroll
        for (int ks = 0; ks < 4; ++ks) {
            uint32_t ah[2][4], al[2][4];
#pragma unroll
            for (int mi = 0; mi < 2; ++mi) {
                const uint32_t pa =
                    ((uint32_t)((rowA + mi * 16) * 128) + (uint32_t)(ks * 32) + hA) ^ swz;
                LDSM4(ah[mi], aHb + pa);
                LDSM4(al[mi], aLb + pa);
            }
#pragma unroll
            for (int nk = 0; nk < 2; ++nk) {
                const uint32_t pb =
                    ((uint32_t)((rowB0 + nk * 16) * 128) + (uint32_t)(ks * 32) + hB) ^ swz;
                uint32_t bh[4], bl[4];
                LDSM4(bh, bHb + pb);
                LDSM4(bl, bLb + pb);
#pragma unroll
                for (int mi = 0; mi < 2; ++mi) {
                    MMA_F16_F32(acc[mi][nk * 2 + 0], ah[mi], bh[0], bh[1]);
                    MMA_F16_F32(acc[mi][nk * 2 + 1], ah[mi], bh[2], bh[3]);
                    MMA_F16_F16(accC[mi][nk * 2 + 0], ah[mi], bl[0], bl[1]);
                    MMA_F16_F16(accC[mi][nk * 2 + 1], ah[mi], bl[2], bl[3]);
                    MMA_F16_F16(accC[mi][nk * 2 + 0], al[mi], bh[0], bh[1]);
                    MMA_F16_F16(accC[mi][nk * 2 + 1], al[mi], bh[2], bh[3]);
                }
            }
        }
    }

    const float cs = 1.0f / LO_SCALE;
    const int gm0 = mb * 128 + wm * 32 + (l >> 2);
    const int gn0 = nb * 128 + wn * 32 + (l & 3) * 2;
#pragma unroll
    for (int mi = 0; mi < 2; ++mi) {
#pragma unroll
        for (int nk = 0; nk < 2; ++nk) {
#pragma unroll
            for (int hf = 0; hf < 2; ++hf) {
                const int n = gn0 + nk * 16 + hf * 8;
                const float b0 = bias[n], b1 = bias[n + 1];
                const float* a = acc[mi][nk * 2 + hf];
                const uint32_t* c = accC[mi][nk * 2 + hf];
                const __half2 c0 = *(const __half2*)&c[0];
                const __half2 c1 = *(const __half2*)&c[1];
                float* p = P + (size_t)(gm0 + mi * 16) * FDIM + n;
                float2 v0, v1;
                v0.x = a[0] + __half2float(__low2half(c0))  * cs + b0;
                v0.y = a[1] + __half2float(__high2half(c0)) * cs + b1;
                v1.x = a[2] + __half2float(__low2half(c1))  * cs + b0;
                v1.y = a[3] + __half2float(__high2half(c1)) * cs + b1;
                *(float2*)p = v0;
                *(float2*)(p + (size_t)8 * FDIM) = v1;
            }
        }
    }
}

// ---------------------------------------------------------------------------
// Similarity GEMM, single-term fp16 (f32 accum). CTA tile 128x256, 16 warps.
// ASYNC pipeline: per-stage full (tx) + consumed (count 512) mbarriers.
// 4 stages x 48 KB.  (R9 kernel — best measured configuration.)
// ---------------------------------------------------------------------------
__global__ void __launch_bounds__(512, 1)
sim_mma(const char* __restrict__ Ah, const char* __restrict__ Bh,
        float* __restrict__ S)
{
    extern __shared__ char smem_raw[];
    const uint32_t sbase = sm_u32(smem_raw);
    const uint32_t full0 = sbase;            // 4 x 8B
    const uint32_t cons0 = sbase + 32;       // 4 x 8B
    const uint32_t data0 = (sbase + 64u + 1023u) & ~1023u;

    const int tid = threadIdx.x;
    const int w = tid >> 5, l = tid & 31;
    const int wm = w & 3;
    const int wn = w >> 2;
    const int mb = blockIdx.x;    // 0..7
    const int nb = blockIdx.y;    // 0..127

    if (tid == 0) {
#pragma unroll
        for (int s = 0; s < NSTAGES_S; ++s) {
            asm volatile("mbarrier.init.shared.b64 [%0], 1;"   :: "r"(full0 + s * 8) : "memory");
            asm volatile("mbarrier.init.shared.b64 [%0], 512;" :: "r"(cons0 + s * 8) : "memory");
        }
    }
    __syncthreads();

    const int rowA  = wm * 32 + (l & 15);
    const uint32_t hA = (uint32_t)(l >> 4) << 4;
    const int rowB0 = (wn & 1) * 64 + (l & 7) + ((l & 16) >> 1);
    const uint32_t hB = (uint32_t)(l & 8) << 1;
    const uint32_t swz = (uint32_t)(l & 7) << 4;
    const uint32_t bsel = (uint32_t)(wn >> 1) * TILE_B;

    float acc[2][8][4];
#pragma unroll
    for (int i = 0; i < 2; ++i)
#pragma unroll
        for (int j = 0; j < 8; ++j)
#pragma unroll
            for (int q = 0; q < 4; ++q) acc[i][j][q] = 0.f;

    auto issue = [&](int kc, int s) {
        const uint32_t d = data0 + s * STAGE_S;
        const uint32_t bar = full0 + s * 8;
        const size_t aoff  = ((size_t)mb * KCHUNKS + kc) * TILE_B;
        const size_t boff0 = ((size_t)(nb * 2 + 0) * KCHUNKS + kc) * TILE_B;
        const size_t boff1 = ((size_t)(nb * 2 + 1) * KCHUNKS + kc) * TILE_B;
        asm volatile("mbarrier.arrive.expect_tx.shared.b64 _, [%0], %1;"
                     :: "r"(bar), "r"((uint32_t)STAGE_S) : "memory");
        BULK_LOAD(d,              Ah + aoff,  bar);
        BULK_LOAD(d + 1 * TILE_B, Bh + boff0, bar);
        BULK_LOAD(d + 2 * TILE_B, Bh + boff1, bar);
    };

    if (tid == 0) { issue(0, 0); issue(1, 1); issue(2, 2); }

    int phf[NSTAGES_S] = {0, 0, 0, 0};
    int phc[NSTAGES_S] = {0, 0, 0, 0};   // used by tid 0 only

    for (int kc = 0; kc < KCHUNKS; ++kc) {
        const int s = kc & 3;
        mbar_wait(full0 + s * 8, phf[s]);
        phf[s] ^= 1;

        const uint32_t aHb = data0 + s * STAGE_S;
        const uint32_t bHb = aHb + TILE_B + bsel;

#pragma unroll
        for (int ks = 0; ks < 4; ++ks) {
            uint32_t ah[2][4];
#pragma unroll
            for (int mi = 0; mi < 2; ++mi) {
                const uint32_t pa =
                    ((uint32_t)((rowA + mi * 16) * 128) + (uint32_t)(ks * 32) + hA) ^ swz;
                LDSM4(ah[mi], aHb + pa);
            }
#pragma unroll
            for (int nk = 0; nk < 4; ++nk) {
                const uint32_t pb =
                    ((uint32_t)((rowB0 + nk * 16) * 128) + (uint32_t)(ks * 32) + hB) ^ swz;
                uint32_t bh[4];
                LDSM4(bh, bHb + pb);
#pragma unroll
                for (int mi = 0; mi < 2; ++mi) {
                    MMA_F16_F32(acc[mi][nk * 2 + 0], ah[mi], bh[0], bh[1]);
                    MMA_F16_F32(acc[mi][nk * 2 + 1], ah[mi], bh[2], bh[3]);
                }
            }
        }

        MBAR_ARRIVE(cons0 + s * 8);

        if (tid == 0 && kc + 3 < KCHUNKS) {
            const int s2 = (kc + 3) & 3;
            if (kc >= 1) {
                mbar_wait(cons0 + s2 * 8, phc[s2]);
                phc[s2] ^= 1;
            }
            issue(kc + 3, s2);
        }
    }

    const int gm0 = mb * 128 + wm * 32 + (l >> 2);
    const int gn0 = nb * 256 + wn * 64 + (l & 3) * 2;
#pragma unroll
    for (int mi = 0; mi < 2; ++mi) {
#pragma unroll
        for (int nk = 0; nk < 4; ++nk) {
#pragma unroll
            for (int hf = 0; hf < 2; ++hf) {
                const float* a = acc[mi][nk * 2 + hf];
                float* p = S + (size_t)(gm0 + mi * 16) * NCONCEPT + gn0 + nk * 16 + hf * 8;
                float2 v0, v1;
                v0.x = a[0]; v0.y = a[1];
                v1.x = a[2]; v1.y = a[3];
                *(float2*)p = v0;
                *(float2*)(p + (size_t)8 * NCONCEPT) = v1;
            }
        }
    }
}

// ---------------------------------------------------------------------------
// Per-row softmax(sim * INV_T) + argmax, row staged in SMEM (single S read).
// One CTA (512 threads) per row; 128 KB dynamic smem.
// ---------------------------------------------------------------------------
__global__ void __launch_bounds__(512)
softmax_row(const float* __restrict__ S,
            float* __restrict__ act,
            float* __restrict__ bidx)
{
    extern __shared__ float srow[];
    const int row = blockIdx.x;
    const int tid = threadIdx.x;
    const float4* s4 = (const float4*)(S + (size_t)row * NCONCEPT);
    float4* r4 = (float4*)srow;

    float m = -INFINITY;
    float Z = 0.f;
    int   bi = 0;

    for (int j = tid; j < NCONCEPT / 4; j += 512) {
        const float4 v = s4[j];
        r4[j] = v;
        const float x[4] = {v.x, v.y, v.z, v.w};
#pragma unroll
        for (int q = 0; q < 4; ++q) {
            if (x[q] > m) {
                Z = Z * __expf((m - x[q]) * INV_T) + 1.0f;
                m = x[q];
                bi = j * 4 + q;
            } else {
                Z += __expf((x[q] - m) * INV_T);
            }
        }
    }

    __shared__ float sm[512];
    __shared__ float sz[512];
    __shared__ int   si[512];
    sm[tid] = m; sz[tid] = Z; si[tid] = bi;
    __syncthreads();

#pragma unroll
    for (int off = 256; off > 0; off >>= 1) {
        if (tid < off) {
            const float m1 = sm[tid],       z1 = sz[tid];
            const float m2 = sm[tid + off], z2 = sz[tid + off];
            const int   i1 = si[tid],       i2 = si[tid + off];
            if (m2 > m1 || (m2 == m1 && i2 < i1)) {
                sm[tid] = m2;
                sz[tid] = z2 + z1 * __expf((m1 - m2) * INV_T);
                si[tid] = i2;
            } else {
                sz[tid] = z1 + z2 * __expf((m2 - m1) * INV_T);
            }
        }
        __syncthreads();
    }

    const float M    = sm[0];
    const float invZ = 1.0f / sz[0];
    float4* a4 = (float4*)(act + (size_t)row * NCONCEPT);
    for (int j = tid; j < NCONCEPT / 4; j += 512) {
        const float4 v = r4[j];
        float4 o;
        o.x = __expf((v.x - M) * INV_T) * invZ;
        o.y = __expf((v.y - M) * INV_T) * invZ;
        o.z = __expf((v.z - M) * INV_T) * invZ;
        o.w = __expf((v.w - M) * INV_T) * invZ;
        a4[j] = o;
    }

    if (tid == 0) bidx[row] = (float)si[0];
}

// ---------------------------------------------------------------------------
extern "C" void kernel_launch(void* const* d_in, const int* in_sizes, int n_in,
                              void* d_out, int out_size)
{
    const float* features   = (const float*)d_in[0];  // [1024, 1024]
    const float* W          = (const float*)d_in[1];  // [1024, 1024]
    const float* b          = (const float*)d_in[2];  // [1024]
    const float* prototypes = (const float*)d_in[3];  // [32768, 1024]

    float* out  = (float*)d_out;
    float* act  = out;                                   // [1024, 32768]
    float* bidx = out + (size_t)BATCH * NCONCEPT;        // [1024] as float

    float *pP = nullptr, *pS = nullptr;
    char *pFh = nullptr, *pFl = nullptr, *pWh = nullptr, *pWl = nullptr;
    char *pAh = nullptr, *pBh = nullptr;
    cudaGetSymbolAddress((void**)&pP,  g_P);
    cudaGetSymbolAddress((void**)&pS,  g_S);
    cudaGetSymbolAddress((void**)&pFh, g_Fh);
    cudaGetSymbolAddress((void**)&pFl, g_Fl);
    cudaGetSymbolAddress((void**)&pWh, g_Wh);
    cudaGetSymbolAddress((void**)&pWl, g_Wl);
    cudaGetSymbolAddress((void**)&pAh, g_Ah);
    cudaGetSymbolAddress((void**)&pBh, g_Bh);

    cudaFuncSetAttribute(proj_mma, cudaFuncAttributeMaxDynamicSharedMemorySize, SMEM_PROJ);
    cudaFuncSetAttribute(sim_mma,  cudaFuncAttributeMaxDynamicSharedMemorySize, SMEM_SIM);
    cudaFuncSetAttribute(softmax_row, cudaFuncAttributeMaxDynamicSharedMemorySize, SMEM_SOFT);

    // Side stream + fork/join events for overlapping convert_b (memory-bound,
    // independent) with the projection chain (tensor-bound). Handles are
    // host-side resources (no device memory), created fresh per call; the
    // fork/join event pattern is graph-capture-legal.
    cudaStream_t sB = nullptr;
    cudaEvent_t evFork = nullptr, evJoin = nullptr;
    cudaStreamCreateWithFlags(&sB, cudaStreamNonBlocking);
    cudaEventCreateWithFlags(&evFork, cudaEventDisableTiming);
    cudaEventCreateWithFlags(&evJoin, cudaEventDisableTiming);

    // Fork: convert_b runs on sB in parallel with the projection chain.
    cudaEventRecord(evFork, 0);
    cudaStreamWaitEvent(sB, evFork, 0);
    convert_b<<<(NCONCEPT * FDIM / 4) / 256, 256, 0, sB>>>(
        (const float4*)prototypes, pBh);

    // Projection chain on the default stream:
    convert_split2<<<(BATCH * FDIM / 4) / 256, 256>>>((const float4*)features, pFh, pFl);
    convert_split2<<<(FDIM * FDIM / 4) / 256, 256>>>((const float4*)W, pWh, pWl);
    proj_mma<<<dim3(BATCH / 128, FDIM / 128), 512, SMEM_PROJ>>>(
        pFh, pFl, pWh, pWl, b, pP);
    convert_a<<<BATCH, 256>>>((const float4*)pP, pAh);

    // Join: sim needs both Ah (default stream) and Bh (sB).
    cudaEventRecord(evJoin, sB);
    cudaStreamWaitEvent(0, evJoin, 0);

    // similarities via single-term fp16 mma.sync (R9 kernel)
    sim_mma<<<dim3(BATCH / 128, NCONCEPT / 256), 512, SMEM_SIM>>>(pAh, pBh, pS);

    // per-row softmax(S/T) + argmax (smem-staged, single S read)
    softmax_row<<<BATCH, 512, SMEM_SOFT>>>(pS, act, bidx);
}

// round 15
// speedup vs baseline: 1.1496x; 1.0292x over previous
#include <cuda_runtime.h>
#include <cuda_fp16.h>
#include <math.h>
#include <stdint.h>

// Problem constants
#define BATCH     1024
#define FDIM      1024
#define NCONCEPT  32768
#define INV_T     10.0f   // 1 / 0.1

#define TILE_B    16384          // one 128x64-fp16 swizzled tile (128 rows * 128 B)
#define KCHUNKS   16             // 1024 / 64
#define LO_SCALE  2048.0f        // 2^11

// sim pipeline: A (1 tile) + B (2 tiles) per stage = 48 KB, 4 stages (async)
#define STAGE_S   (3 * TILE_B)
#define NSTAGES_S 4
#define SMEM_SIM  (1024 + NSTAGES_S * STAGE_S)
// proj pipeline: Fhi, Flo, Whi, Wlo per stage = 64 KB, 3 stages
#define STAGE_P   (4 * TILE_B)
#define NSTAGES_P 3
#define SMEM_PROJ (1024 + NSTAGES_P * STAGE_P)
// softmax: full row staged in smem
#define SMEM_SOFT (NCONCEPT * 4)

#define NSLICES   8              // mb slices for sim/softmax overlap

// ---------------- scratch (device globals; no allocation allowed) ----------
__device__ float g_P[BATCH * FDIM];
__device__ float g_S[(size_t)BATCH * NCONCEPT];          // similarities (134 MB)
__device__ __align__(256) char g_Fh[(size_t)BATCH * FDIM * 2];
__device__ __align__(256) char g_Fl[(size_t)BATCH * FDIM * 2];
__device__ __align__(256) char g_Wh[(size_t)FDIM * FDIM * 2];
__device__ __align__(256) char g_Wl[(size_t)FDIM * FDIM * 2];
__device__ __align__(256) char g_Ah[(size_t)BATCH * FDIM * 2];
__device__ __align__(256) char g_Bh[(size_t)NCONCEPT * FDIM * 2];

// ---------------------------------------------------------------------------
// PTX helpers (baseline ISA only)
// ---------------------------------------------------------------------------
__device__ __forceinline__ uint32_t sm_u32(const void* p) {
    uint32_t a;
    asm("{ .reg .u64 t; cvta.to.shared.u64 t, %1; cvt.u32.u64 %0, t; }"
        : "=r"(a) : "l"(p));
    return a;
}

__device__ __forceinline__ void mbar_wait(uint32_t addr, int phase) {
    asm volatile(
        "{\n\t.reg .pred P;\n\t"
        "WL_%=:\n\t"
        "mbarrier.try_wait.parity.acquire.cta.shared::cta.b64 P, [%0], %1, 0x989680;\n\t"
        "@P bra.uni WD_%=;\n\t"
        "bra.uni WL_%=;\n\t"
        "WD_%=:\n\t}"
        :: "r"(addr), "r"((uint32_t)phase) : "memory");
}

#define MBAR_ARRIVE(addr) \
    asm volatile("mbarrier.arrive.shared.b64 _, [%0];" :: "r"(addr) : "memory")

#define LDSM4(R, addr) \
    asm volatile("ldmatrix.sync.aligned.m8n8.x4.shared.b16 {%0,%1,%2,%3}, [%4];" \
        : "=r"((R)[0]), "=r"((R)[1]), "=r"((R)[2]), "=r"((R)[3]) : "r"(addr))

#define MMA_F16_F32(C, A, b0_, b1_) \
    asm volatile("mma.sync.aligned.m16n8k16.row.col.f32.f16.f16.f32 " \
        "{%0,%1,%2,%3}, {%4,%5,%6,%7}, {%8,%9}, {%0,%1,%2,%3};" \
        : "+f"((C)[0]), "+f"((C)[1]), "+f"((C)[2]), "+f"((C)[3]) \
        : "r"((A)[0]), "r"((A)[1]), "r"((A)[2]), "r"((A)[3]), "r"(b0_), "r"(b1_))

#define MMA_F16_F16(C, A, b0_, b1_) \
    asm volatile("mma.sync.aligned.m16n8k16.row.col.f16.f16.f16.f16 " \
        "{%0,%1}, {%2,%3,%4,%5}, {%6,%7}, {%0,%1};" \
        : "+r"((C)[0]), "+r"((C)[1]) \
        : "r"((A)[0]), "r"((A)[1]), "r"((A)[2]), "r"((A)[3]), "r"(b0_), "r"(b1_))

#define BULK_LOAD(dst, src, bar) \
    asm volatile("cp.async.bulk.shared::cluster.global.mbarrier::complete_tx::bytes " \
        "[%0], [%1], %2, [%3];" \
        :: "r"(dst), "l"(src), "r"((uint32_t)TILE_B), "r"(bar) : "memory")

// ---------------------------------------------------------------------------
// fp32 -> fp16 two-limb split into pre-swizzled 128x64 tiles (no norm).
// ---------------------------------------------------------------------------
__global__ void __launch_bounds__(256)
convert_split2(const float4* __restrict__ src, char* __restrict__ hi, char* __restrict__ lo)
{
    const size_t i4 = (size_t)blockIdx.x * 256 + threadIdx.x;
    const int row = (int)(i4 >> 8);
    const int k   = ((int)i4 & 255) * 4;
    const float4 v = src[i4];
    const float x[4] = {v.x, v.y, v.z, v.w};

    unsigned short h[4], l[4];
#pragma unroll
    for (int j = 0; j < 4; ++j) {
        const __half hb = __float2half_rn(x[j]);
        const float r = (x[j] - __half2float(hb)) * LO_SCALE;
        h[j] = __half_as_ushort(hb);
        l[j] = __half_as_ushort(__float2half_rn(r));
    }

    const int tile = (row >> 7) * KCHUNKS + (k >> 6);
    uint32_t off = (uint32_t)((row & 127) * 128 + (k & 63) * 2);
    off ^= (off >> 3) & 0x70;

    uint2 ph, pl;
    ph.x = (uint32_t)h[0] | ((uint32_t)h[1] << 16);
    ph.y = (uint32_t)h[2] | ((uint32_t)h[3] << 16);
    pl.x = (uint32_t)l[0] | ((uint32_t)l[1] << 16);
    pl.y = (uint32_t)l[2] | ((uint32_t)l[3] << 16);
    *(uint2*)(hi + (size_t)tile * TILE_B + off) = ph;
    *(uint2*)(lo + (size_t)tile * TILE_B + off) = pl;
}

// ---------------------------------------------------------------------------
// A-side: fused L2-normalize + fp16 hi limb only. One CTA per row.
// ---------------------------------------------------------------------------
__global__ void __launch_bounds__(256)
convert_a(const float4* __restrict__ src, char* __restrict__ hi)
{
    const int row = blockIdx.x;
    const int tid = threadIdx.x;
    const float4 v = src[(size_t)row * 256 + tid];
    const float x[4] = {v.x, v.y, v.z, v.w};

    __shared__ float red[256];
    red[tid] = x[0]*x[0] + x[1]*x[1] + x[2]*x[2] + x[3]*x[3];
    __syncthreads();
#pragma unroll
    for (int off = 128; off > 0; off >>= 1) {
        if (tid < off) red[tid] += red[tid + off];
        __syncthreads();
    }
    const float inv = 1.0f / fmaxf(sqrtf(red[0]), 1e-12f);

    unsigned short h[4];
#pragma unroll
    for (int j = 0; j < 4; ++j)
        h[j] = __half_as_ushort(__float2half_rn(x[j] * inv));

    const int k = tid * 4;
    const int tile = (row >> 7) * KCHUNKS + (k >> 6);
    uint32_t off = (uint32_t)((row & 127) * 128 + (k & 63) * 2);
    off ^= (off >> 3) & 0x70;

    uint2 ph;
    ph.x = (uint32_t)h[0] | ((uint32_t)h[1] << 16);
    ph.y = (uint32_t)h[2] | ((uint32_t)h[3] << 16);
    *(uint2*)(hi + (size_t)tile * TILE_B + off) = ph;
}

// ---------------------------------------------------------------------------
// B-side: fp16 hi limb only, pre-swizzled tiles.
// ---------------------------------------------------------------------------
__global__ void __launch_bounds__(256)
convert_b(const float4* __restrict__ src, char* __restrict__ hi)
{
    const size_t i4 = (size_t)blockIdx.x * 256 + threadIdx.x;
    const int row = (int)(i4 >> 8);
    const int k   = ((int)i4 & 255) * 4;
    const float4 v = src[i4];
    const float x[4] = {v.x, v.y, v.z, v.w};

    unsigned short h[4];
#pragma unroll
    for (int j = 0; j < 4; ++j)
        h[j] = __half_as_ushort(__float2half_rn(x[j]));

    const int tile = (row >> 7) * KCHUNKS + (k >> 6);
    uint32_t off = (uint32_t)((row & 127) * 128 + (k & 63) * 2);
    off ^= (off >> 3) & 0x70;

    uint2 ph;
    ph.x = (uint32_t)h[0] | ((uint32_t)h[1] << 16);
    ph.y = (uint32_t)h[2] | ((uint32_t)h[3] << 16);
    *(uint2*)(hi + (size_t)tile * TILE_B + off) = ph;
}

// ---------------------------------------------------------------------------
// Projection GEMM, fp16 3-term limbs (~fp32). CTA 128x128, 16 warps.
// ---------------------------------------------------------------------------
__global__ void __launch_bounds__(512, 1)
proj_mma(const char* __restrict__ Fh, const char* __restrict__ Fl,
         const char* __restrict__ Wh, const char* __restrict__ Wl,
         const float* __restrict__ bias, float* __restrict__ P)
{
    extern __shared__ char smem_raw[];
    const uint32_t sbase = sm_u32(smem_raw);
    const uint32_t mbar0 = sbase;
    const uint32_t data0 = (sbase + 32u + 1023u) & ~1023u;

    const int tid = threadIdx.x;
    const int w = tid >> 5, l = tid & 31;
    const int wm = w & 3;
    const int wn = w >> 2;
    const int mb = blockIdx.x;
    const int nb = blockIdx.y;

    if (tid == 0) {
#pragma unroll
        for (int s = 0; s < NSTAGES_P; ++s)
            asm volatile("mbarrier.init.shared.b64 [%0], 1;" :: "r"(mbar0 + s * 8) : "memory");
    }
    __syncthreads();

    const int rowA  = wm * 32 + (l & 15);
    const uint32_t hA = (uint32_t)(l >> 4) << 4;
    const int rowB0 = wn * 32 + (l & 7) + ((l & 16) >> 1);
    const uint32_t hB = (uint32_t)(l & 8) << 1;
    const uint32_t swz = (uint32_t)(l & 7) << 4;

    float    acc[2][4][4];
    uint32_t accC[2][4][2];
#pragma unroll
    for (int i = 0; i < 2; ++i)
#pragma unroll
        for (int j = 0; j < 4; ++j) {
#pragma unroll
            for (int q = 0; q < 4; ++q) acc[i][j][q] = 0.f;
            accC[i][j][0] = 0u; accC[i][j][1] = 0u;
        }

    auto issue = [&](int kc, int s) {
        const uint32_t d = data0 + s * STAGE_P;
        const uint32_t bar = mbar0 + s * 8;
        const size_t aoff = ((size_t)mb * KCHUNKS + kc) * TILE_B;
        const size_t boff = ((size_t)nb * KCHUNKS + kc) * TILE_B;
        asm volatile("mbarrier.arrive.expect_tx.shared.b64 _, [%0], %1;"
                     :: "r"(bar), "r"((uint32_t)STAGE_P) : "memory");
        BULK_LOAD(d,              Fh + aoff, bar);
        BULK_LOAD(d + 1 * TILE_B, Fl + aoff, bar);
        BULK_LOAD(d + 2 * TILE_B, Wh + boff, bar);
        BULK_LOAD(d + 3 * TILE_B, Wl + boff, bar);
    };

    if (tid == 0) { issue(0, 0); issue(1, 1); }

    int ph[NSTAGES_P] = {0, 0, 0};

    for (int kc = 0; kc < KCHUNKS; ++kc) {
        const int s = kc % NSTAGES_P;
        mbar_wait(mbar0 + s * 8, ph[s]);
        ph[s] ^= 1;
        __syncthreads();
        if (tid == 0 && kc + 2 < KCHUNKS) issue(kc + 2, (kc + 2) % NSTAGES_P);

        const uint32_t aHb = data0 + s * STAGE_P;
        const uint32_t aLb = aHb + 1 * TILE_B;
        const uint32_t bHb = aHb + 2 * TILE_B;
        const uint32_t bLb = aHb + 3 * TILE_B;

#pragma unroll
        for (int ks = 0; ks < 4; ++ks) {
            uint32_t ah[2][4], al[2][4];
#pragma unroll
            for (int mi = 0; mi < 2; ++mi) {
                const uint32_t pa =
                    ((uint32_t)((rowA + mi * 16) * 128) + (uint32_t)(ks * 32) + hA) ^ swz;
                LDSM4(ah[mi], aHb + pa);
                LDSM4(al[mi], aLb + pa);
            }
#pragma unroll
            for (int nk = 0; nk < 2; ++nk) {
                const uint32_t pb =
                    ((uint32_t)((rowB0 + nk * 16) * 128) + (uint32_t)(ks * 32) + hB) ^ swz;
                uint32_t bh[4], bl[4];
                LDSM4(bh, bHb + pb);
                LDSM4(bl, bLb + pb);
#pragma unroll
                for (int mi = 0; mi < 2; ++mi) {
                    MMA_F16_F32(acc[mi][nk * 2 + 0], ah[mi], bh[0], bh[1]);
                    MMA_F16_F32(acc[mi][nk * 2 + 1], ah[mi], bh[2], bh[3]);
                    MMA_F16_F16(accC[mi][nk * 2 + 0], ah[mi], bl[0], bl[1]);
                    MMA_F16_F16(accC[mi][nk * 2 + 1], ah[mi], bl[2], bl[3]);
                    MMA_F16_F16(accC[mi][nk * 2 + 0], al[mi], bh[0], bh[1]);
                    MMA_F16_F16(accC[mi][nk * 2 + 1], al[mi], bh[2], bh[3]);
                }
            }
        }
    }

    const float cs = 1.0f / LO_SCALE;
    const int gm0 = mb * 128 + wm * 32 + (l >> 2);
    const int gn0 = nb * 128 + wn * 32 + (l & 3) * 2;
#pragma unroll
    for (int mi = 0; mi < 2; ++mi) {
#pragma unroll
        for (int nk = 0; nk < 2; ++nk) {
#pragma unroll
            for (int hf = 0; hf < 2; ++hf) {
                const int n = gn0 + nk * 16 + hf * 8;
                const float b0 = bias[n], b1 = bias[n + 1];
                const float* a = acc[mi][nk * 2 + hf];
                const uint32_t* c = accC[mi][nk * 2 + hf];
                const __half2 c0 = *(const __half2*)&c[0];
                const __half2 c1 = *(const __half2*)&c[1];
                float* p = P + (size_t)(gm0 + mi * 16) * FDIM + n;
                float2 v0, v1;
                v0.x = a[0] + __half2float(__low2half(c0))  * cs + b0;
                v0.y = a[1] + __half2float(__high2half(c0)) * cs + b1;
                v1.x = a[2] + __half2float(__low2half(c1))  * cs + b0;
                v1.y = a[3] + __half2float(__high2half(c1)) * cs + b1;
                *(float2*)p = v0;
                *(float2*)(p + (size_t)8 * FDIM) = v1;
            }
        }
    }
}

// ---------------------------------------------------------------------------
// Similarity GEMM slice (one mb block of 128 rows), single-term fp16
// (f32 accum). CTA tile 128x256, 16 warps. Async full/cons mbarrier pipeline,
// 4 stages x 48 KB. Grid (1, 128); mb passed as an argument.
// ---------------------------------------------------------------------------
__global__ void __launch_bounds__(512, 1)
sim_mma(const char* __restrict__ Ah, const char* __restrict__ Bh,
        float* __restrict__ S, int mb)
{
    extern __shared__ char smem_raw[];
    const uint32_t sbase = sm_u32(smem_raw);
    const uint32_t full0 = sbase;            // 4 x 8B
    const uint32_t cons0 = sbase + 32;       // 4 x 8B
    const uint32_t data0 = (sbase + 64u + 1023u) & ~1023u;

    const int tid = threadIdx.x;
    const int w = tid >> 5, l = tid & 31;
    const int wm = w & 3;
    const int wn = w >> 2;
    const int nb = blockIdx.y;    // 0..127

    if (tid == 0) {
#pragma unroll
        for (int s = 0; s < NSTAGES_S; ++s) {
            asm volatile("mbarrier.init.shared.b64 [%0], 1;"   :: "r"(full0 + s * 8) : "memory");
            asm volatile("mbarrier.init.shared.b64 [%0], 512;" :: "r"(cons0 + s * 8) : "memory");
        }
    }
    __syncthreads();

    const int rowA  = wm * 32 + (l & 15);
    const uint32_t hA = (uint32_t)(l >> 4) << 4;
    const int rowB0 = (wn & 1) * 64 + (l & 7) + ((l & 16) >> 1);
    const uint32_t hB = (uint32_t)(l & 8) << 1;
    const uint32_t swz = (uint32_t)(l & 7) << 4;
    const uint32_t bsel = (uint32_t)(wn >> 1) * TILE_B;

    float acc[2][8][4];
#pragma unroll
    for (int i = 0; i < 2; ++i)
#pragma unroll
        for (int j = 0; j < 8; ++j)
#pragma unroll
            for (int q = 0; q < 4; ++q) acc[i][j][q] = 0.f;

    auto issue = [&](int kc, int s) {
        const uint32_t d = data0 + s * STAGE_S;
        const uint32_t bar = full0 + s * 8;
        const size_t aoff  = ((size_t)mb * KCHUNKS + kc) * TILE_B;
        const size_t boff0 = ((size_t)(nb * 2 + 0) * KCHUNKS + kc) * TILE_B;
        const size_t boff1 = ((size_t)(nb * 2 + 1) * KCHUNKS + kc) * TILE_B;
        asm volatile("mbarrier.arrive.expect_tx.shared.b64 _, [%0], %1;"
                     :: "r"(bar), "r"((uint32_t)STAGE_S) : "memory");
        BULK_LOAD(d,              Ah + aoff,  bar);
        BULK_LOAD(d + 1 * TILE_B, Bh + boff0, bar);
        BULK_LOAD(d + 2 * TILE_B, Bh + boff1, bar);
    };

    if (tid == 0) { issue(0, 0); issue(1, 1); issue(2, 2); }

    int phf[NSTAGES_S] = {0, 0, 0, 0};
    int phc[NSTAGES_S] = {0, 0, 0, 0};   // used by tid 0 only

    for (int kc = 0; kc < KCHUNKS; ++kc) {
        const int s = kc & 3;
        mbar_wait(full0 + s * 8, phf[s]);
        phf[s] ^= 1;

        const uint32_t aHb = data0 + s * STAGE_S;
        const uint32_t bHb = aHb + TILE_B + bsel;

#pragma unroll
        for (int ks = 0; ks < 4; ++ks) {
            uint32_t ah[2][4];
#pragma unroll
            for (int mi = 0; mi < 2; ++mi) {
                const uint32_t pa =
                    ((uint32_t)((rowA + mi * 16) * 128) + (uint32_t)(ks * 32) + hA) ^ swz;
                LDSM4(ah[mi], aHb + pa);
            }
#pragma unroll
            for (int nk = 0; nk < 4; ++nk) {
                const uint32_t pb =
                    ((uint32_t)((rowB0 + nk * 16) * 128) + (uint32_t)(ks * 32) + hB) ^ swz;
                uint32_t bh[4];
                LDSM4(bh, bHb + pb);
#pragma unroll
                for (int mi = 0; mi < 2; ++mi) {
                    MMA_F16_F32(acc[mi][nk * 2 + 0], ah[mi], bh[0], bh[1]);
                    MMA_F16_F32(acc[mi][nk * 2 + 1], ah[mi], bh[2], bh[3]);
                }
            }
        }

        MBAR_ARRIVE(cons0 + s * 8);

        if (tid == 0 && kc + 3 < KCHUNKS) {
            const int s2 = (kc + 3) & 3;
            if (kc >= 1) {
                mbar_wait(cons0 + s2 * 8, phc[s2]);
                phc[s2] ^= 1;
            }
            issue(kc + 3, s2);
        }
    }

    const int gm0 = mb * 128 + wm * 32 + (l >> 2);
    const int gn0 = nb * 256 + wn * 64 + (l & 3) * 2;
#pragma unroll
    for (int mi = 0; mi < 2; ++mi) {
#pragma unroll
        for (int nk = 0; nk < 4; ++nk) {
#pragma unroll
            for (int hf = 0; hf < 2; ++hf) {
                const float* a = acc[mi][nk * 2 + hf];
                float* p = S + (size_t)(gm0 + mi * 16) * NCONCEPT + gn0 + nk * 16 + hf * 8;
                float2 v0, v1;
                v0.x = a[0]; v0.y = a[1];
                v1.x = a[2]; v1.y = a[3];
                *(float2*)p = v0;
                *(float2*)(p + (size_t)8 * NCONCEPT) = v1;
            }
        }
    }
}

// ---------------------------------------------------------------------------
// Per-row softmax(sim * INV_T) + argmax, row staged in SMEM (single S read).
// One CTA (512 threads) per row; 128 KB dynamic smem. row = row_base + blockIdx.x.
// ---------------------------------------------------------------------------
__global__ void __launch_bounds__(512)
softmax_row(const float* __restrict__ S,
            float* __restrict__ act,
            float* __restrict__ bidx,
            int row_base)
{
    extern __shared__ float srow[];
    const int row = row_base + blockIdx.x;
    const int tid = threadIdx.x;
    const float4* s4 = (const float4*)(S + (size_t)row * NCONCEPT);
    float4* r4 = (float4*)srow;

    float m = -INFINITY;
    float Z = 0.f;
    int   bi = 0;

    for (int j = tid; j < NCONCEPT / 4; j += 512) {
        const float4 v = s4[j];
        r4[j] = v;
        const float x[4] = {v.x, v.y, v.z, v.w};
#pragma unroll
        for (int q = 0; q < 4; ++q) {
            if (x[q] > m) {
                Z = Z * __expf((m - x[q]) * INV_T) + 1.0f;
                m = x[q];
                bi = j * 4 + q;
            } else {
                Z += __expf((x[q] - m) * INV_T);
            }
        }
    }

    __shared__ float sm[512];
    __shared__ float sz[512];
    __shared__ int   si[512];
    sm[tid] = m; sz[tid] = Z; si[tid] = bi;
    __syncthreads();

#pragma unroll
    for (int off = 256; off > 0; off >>= 1) {
        if (tid < off) {
            const float m1 = sm[tid],       z1 = sz[tid];
            const float m2 = sm[tid + off], z2 = sz[tid + off];
            const int   i1 = si[tid],       i2 = si[tid + off];
            if (m2 > m1 || (m2 == m1 && i2 < i1)) {
                sm[tid] = m2;
                sz[tid] = z2 + z1 * __expf((m1 - m2) * INV_T);
                si[tid] = i2;
            } else {
                sz[tid] = z1 + z2 * __expf((m2 - m1) * INV_T);
            }
        }
        __syncthreads();
    }

    const float M    = sm[0];
    const float invZ = 1.0f / sz[0];
    float4* a4 = (float4*)(act + (size_t)row * NCONCEPT);
    for (int j = tid; j < NCONCEPT / 4; j += 512) {
        const float4 v = r4[j];
        float4 o;
        o.x = __expf((v.x - M) * INV_T) * invZ;
        o.y = __expf((v.y - M) * INV_T) * invZ;
        o.z = __expf((v.z - M) * INV_T) * invZ;
        o.w = __expf((v.w - M) * INV_T) * invZ;
        a4[j] = o;
    }

    if (tid == 0) bidx[row] = (float)si[0];
}

// ---------------------------------------------------------------------------
extern "C" void kernel_launch(void* const* d_in, const int* in_sizes, int n_in,
                              void* d_out, int out_size)
{
    const float* features   = (const float*)d_in[0];  // [1024, 1024]
    const float* W          = (const float*)d_in[1];  // [1024, 1024]
    const float* b          = (const float*)d_in[2];  // [1024]
    const float* prototypes = (const float*)d_in[3];  // [32768, 1024]

    float* out  = (float*)d_out;
    float* act  = out;                                   // [1024, 32768]
    float* bidx = out + (size_t)BATCH * NCONCEPT;        // [1024] as float

    float *pP = nullptr, *pS = nullptr;
    char *pFh = nullptr, *pFl = nullptr, *pWh = nullptr, *pWl = nullptr;
    char *pAh = nullptr, *pBh = nullptr;
    cudaGetSymbolAddress((void**)&pP,  g_P);
    cudaGetSymbolAddress((void**)&pS,  g_S);
    cudaGetSymbolAddress((void**)&pFh, g_Fh);
    cudaGetSymbolAddress((void**)&pFl, g_Fl);
    cudaGetSymbolAddress((void**)&pWh, g_Wh);
    cudaGetSymbolAddress((void**)&pWl, g_Wl);
    cudaGetSymbolAddress((void**)&pAh, g_Ah);
    cudaGetSymbolAddress((void**)&pBh, g_Bh);

    cudaFuncSetAttribute(proj_mma, cudaFuncAttributeMaxDynamicSharedMemorySize, SMEM_PROJ);
    cudaFuncSetAttribute(sim_mma,  cudaFuncAttributeMaxDynamicSharedMemorySize, SMEM_SIM);
    cudaFuncSetAttribute(softmax_row, cudaFuncAttributeMaxDynamicSharedMemorySize, SMEM_SOFT);

    // ONE extra stream + four events — the exact resource budget proven
    // delta=0 in R13. Slices alternate between the default stream and sB so
    // each slice's softmax overlaps the other stream's next sim slice.
    cudaStream_t sB = nullptr;
    cudaEvent_t evFork = nullptr, evA = nullptr, evB = nullptr, evJoin = nullptr;
    cudaStreamCreateWithFlags(&sB, cudaStreamNonBlocking);
    cudaEventCreateWithFlags(&evFork, cudaEventDisableTiming);
    cudaEventCreateWithFlags(&evA, cudaEventDisableTiming);
    cudaEventCreateWithFlags(&evB, cudaEventDisableTiming);
    cudaEventCreateWithFlags(&evJoin, cudaEventDisableTiming);

    // Fork: convert_b on sB in parallel with the projection chain.
    cudaEventRecord(evFork, 0);
    cudaStreamWaitEvent(sB, evFork, 0);
    convert_b<<<(NCONCEPT * FDIM / 4) / 256, 256, 0, sB>>>(
        (const float4*)prototypes, pBh);
    cudaEventRecord(evB, sB);

    // Projection chain on the default stream:
    convert_split2<<<(BATCH * FDIM / 4) / 256, 256>>>((const float4*)features, pFh, pFl);
    convert_split2<<<(FDIM * FDIM / 4) / 256, 256>>>((const float4*)W, pWh, pWl);
    proj_mma<<<dim3(BATCH / 128, FDIM / 128), 512, SMEM_PROJ>>>(
        pFh, pFl, pWh, pWl, b, pP);
    convert_a<<<BATCH, 256>>>((const float4*)pP, pAh);
    cudaEventRecord(evA, 0);

    // Cross deps: default stream needs Bh; sB needs Ah.
    cudaStreamWaitEvent(0, evB, 0);
    cudaStreamWaitEvent(sB, evA, 0);

    // Interleaved sim/softmax slices across the two streams.
    for (int i = 0; i < NSLICES; ++i) {
        cudaStream_t s = (i & 1) ? sB : (cudaStream_t)0;
        sim_mma<<<dim3(1, NCONCEPT / 256), 512, SMEM_SIM, s>>>(pAh, pBh, pS, i);
        softmax_row<<<BATCH / NSLICES, 512, SMEM_SOFT, s>>>(pS, act, bidx, i * 128);
    }

    // Join sB back into the default stream.
    cudaEventRecord(evJoin, sB);
    cudaStreamWaitEvent(0, evJoin, 0);
}

// round 16
// speedup vs baseline: 1.1963x; 1.0407x over previous
#include <cuda_runtime.h>
#include <cuda_fp16.h>
#include <math.h>
#include <stdint.h>

// Problem constants
#define BATCH     1024
#define FDIM      1024
#define NCONCEPT  32768
#define INV_T     10.0f   // 1 / 0.1

#define TILE_B    16384          // one 128x64-fp16 swizzled tile (128 rows * 128 B)
#define HTILE_B   8192           // half tile: 64 rows (contiguous within a tile)
#define KCHUNKS   16             // 1024 / 64
#define LO_SCALE  2048.0f        // 2^11

// sim pipeline: A (1 tile) + B (2 tiles) per stage = 48 KB, 4 stages (async)
#define STAGE_S   (3 * TILE_B)
#define NSTAGES_S 4
#define SMEM_SIM  (1024 + NSTAGES_S * STAGE_S)
// proj pipeline: Fh+Fl tiles + Wh+Wl half-tiles = 48 KB, 3 stages
#define STAGE_P   (2 * TILE_B + 2 * HTILE_B)
#define NSTAGES_P 3
#define SMEM_PROJ (1024 + NSTAGES_P * STAGE_P)
// softmax: full row staged in smem
#define SMEM_SOFT (NCONCEPT * 4)

#define NSLICES   8              // mb slices for sim/softmax overlap

// ---------------- scratch (device globals; no allocation allowed) ----------
__device__ float g_P[BATCH * FDIM];
__device__ float g_S[(size_t)BATCH * NCONCEPT];          // similarities (134 MB)
__device__ __align__(256) char g_Fh[(size_t)BATCH * FDIM * 2];
__device__ __align__(256) char g_Fl[(size_t)BATCH * FDIM * 2];
__device__ __align__(256) char g_Wh[(size_t)FDIM * FDIM * 2];
__device__ __align__(256) char g_Wl[(size_t)FDIM * FDIM * 2];
__device__ __align__(256) char g_Ah[(size_t)BATCH * FDIM * 2];
__device__ __align__(256) char g_Bh[(size_t)NCONCEPT * FDIM * 2];

// ---------------------------------------------------------------------------
// PTX helpers (baseline ISA only)
// ---------------------------------------------------------------------------
__device__ __forceinline__ uint32_t sm_u32(const void* p) {
    uint32_t a;
    asm("{ .reg .u64 t; cvta.to.shared.u64 t, %1; cvt.u32.u64 %0, t; }"
        : "=r"(a) : "l"(p));
    return a;
}

__device__ __forceinline__ void mbar_wait(uint32_t addr, int phase) {
    asm volatile(
        "{\n\t.reg .pred P;\n\t"
        "WL_%=:\n\t"
        "mbarrier.try_wait.parity.acquire.cta.shared::cta.b64 P, [%0], %1, 0x989680;\n\t"
        "@P bra.uni WD_%=;\n\t"
        "bra.uni WL_%=;\n\t"
        "WD_%=:\n\t}"
        :: "r"(addr), "r"((uint32_t)phase) : "memory");
}

#define MBAR_ARRIVE(addr) \
    asm volatile("mbarrier.arrive.shared.b64 _, [%0];" :: "r"(addr) : "memory")

#define LDSM4(R, addr) \
    asm volatile("ldmatrix.sync.aligned.m8n8.x4.shared.b16 {%0,%1,%2,%3}, [%4];" \
        : "=r"((R)[0]), "=r"((R)[1]), "=r"((R)[2]), "=r"((R)[3]) : "r"(addr))

#define MMA_F16_F32(C, A, b0_, b1_) \
    asm volatile("mma.sync.aligned.m16n8k16.row.col.f32.f16.f16.f32 " \
        "{%0,%1,%2,%3}, {%4,%5,%6,%7}, {%8,%9}, {%0,%1,%2,%3};" \
        : "+f"((C)[0]), "+f"((C)[1]), "+f"((C)[2]), "+f"((C)[3]) \
        : "r"((A)[0]), "r"((A)[1]), "r"((A)[2]), "r"((A)[3]), "r"(b0_), "r"(b1_))

#define MMA_F16_F16(C, A, b0_, b1_) \
    asm volatile("mma.sync.aligned.m16n8k16.row.col.f16.f16.f16.f16 " \
        "{%0,%1}, {%2,%3,%4,%5}, {%6,%7}, {%0,%1};" \
        : "+r"((C)[0]), "+r"((C)[1]) \
        : "r"((A)[0]), "r"((A)[1]), "r"((A)[2]), "r"((A)[3]), "r"(b0_), "r"(b1_))

#define BULK_LOAD(dst, src, bar) \
    asm volatile("cp.async.bulk.shared::cluster.global.mbarrier::complete_tx::bytes " \
        "[%0], [%1], %2, [%3];" \
        :: "r"(dst), "l"(src), "r"((uint32_t)TILE_B), "r"(bar) : "memory")

#define BULK_LOAD_SZ(dst, src, bar, sz) \
    asm volatile("cp.async.bulk.shared::cluster.global.mbarrier::complete_tx::bytes " \
        "[%0], [%1], %2, [%3];" \
        :: "r"(dst), "l"(src), "r"((uint32_t)(sz)), "r"(bar) : "memory")

// ---------------------------------------------------------------------------
// fp32 -> fp16 two-limb split into pre-swizzled 128x64 tiles (no norm).
// ---------------------------------------------------------------------------
__global__ void __launch_bounds__(256)
convert_split2(const float4* __restrict__ src, char* __restrict__ hi, char* __restrict__ lo)
{
    const size_t i4 = (size_t)blockIdx.x * 256 + threadIdx.x;
    const int row = (int)(i4 >> 8);
    const int k   = ((int)i4 & 255) * 4;
    const float4 v = src[i4];
    const float x[4] = {v.x, v.y, v.z, v.w};

    unsigned short h[4], l[4];
#pragma unroll
    for (int j = 0; j < 4; ++j) {
        const __half hb = __float2half_rn(x[j]);
        const float r = (x[j] - __half2float(hb)) * LO_SCALE;
        h[j] = __half_as_ushort(hb);
        l[j] = __half_as_ushort(__float2half_rn(r));
    }

    const int tile = (row >> 7) * KCHUNKS + (k >> 6);
    uint32_t off = (uint32_t)((row & 127) * 128 + (k & 63) * 2);
    off ^= (off >> 3) & 0x70;

    uint2 ph, pl;
    ph.x = (uint32_t)h[0] | ((uint32_t)h[1] << 16);
    ph.y = (uint32_t)h[2] | ((uint32_t)h[3] << 16);
    pl.x = (uint32_t)l[0] | ((uint32_t)l[1] << 16);
    pl.y = (uint32_t)l[2] | ((uint32_t)l[3] << 16);
    *(uint2*)(hi + (size_t)tile * TILE_B + off) = ph;
    *(uint2*)(lo + (size_t)tile * TILE_B + off) = pl;
}

// ---------------------------------------------------------------------------
// A-side: fused L2-normalize + fp16 hi limb only. One CTA per row.
// ---------------------------------------------------------------------------
__global__ void __launch_bounds__(256)
convert_a(const float4* __restrict__ src, char* __restrict__ hi)
{
    const int row = blockIdx.x;
    const int tid = threadIdx.x;
    const float4 v = src[(size_t)row * 256 + tid];
    const float x[4] = {v.x, v.y, v.z, v.w};

    __shared__ float red[256];
    red[tid] = x[0]*x[0] + x[1]*x[1] + x[2]*x[2] + x[3]*x[3];
    __syncthreads();
#pragma unroll
    for (int off = 128; off > 0; off >>= 1) {
        if (tid < off) red[tid] += red[tid + off];
        __syncthreads();
    }
    const float inv = 1.0f / fmaxf(sqrtf(red[0]), 1e-12f);

    unsigned short h[4];
#pragma unroll
    for (int j = 0; j < 4; ++j)
        h[j] = __half_as_ushort(__float2half_rn(x[j] * inv));

    const int k = tid * 4;
    const int tile = (row >> 7) * KCHUNKS + (k >> 6);
    uint32_t off = (uint32_t)((row & 127) * 128 + (k & 63) * 2);
    off ^= (off >> 3) & 0x70;

    uint2 ph;
    ph.x = (uint32_t)h[0] | ((uint32_t)h[1] << 16);
    ph.y = (uint32_t)h[2] | ((uint32_t)h[3] << 16);
    *(uint2*)(hi + (size_t)tile * TILE_B + off) = ph;
}

// ---------------------------------------------------------------------------
// B-side: fp16 hi limb only, pre-swizzled tiles.
// ---------------------------------------------------------------------------
__global__ void __launch_bounds__(256)
convert_b(const float4* __restrict__ src, char* __restrict__ hi)
{
    const size_t i4 = (size_t)blockIdx.x * 256 + threadIdx.x;
    const int row = (int)(i4 >> 8);
    const int k   = ((int)i4 & 255) * 4;
    const float4 v = src[i4];
    const float x[4] = {v.x, v.y, v.z, v.w};

    unsigned short h[4];
#pragma unroll
    for (int j = 0; j < 4; ++j)
        h[j] = __half_as_ushort(__float2half_rn(x[j]));

    const int tile = (row >> 7) * KCHUNKS + (k >> 6);
    uint32_t off = (uint32_t)((row & 127) * 128 + (k & 63) * 2);
    off ^= (off >> 3) & 0x70;

    uint2 ph;
    ph.x = (uint32_t)h[0] | ((uint32_t)h[1] << 16);
    ph.y = (uint32_t)h[2] | ((uint32_t)h[3] << 16);
    *(uint2*)(hi + (size_t)tile * TILE_B + off) = ph;
}

// ---------------------------------------------------------------------------
// Projection GEMM, fp16 3-term limbs (~fp32). CTA 128x64, 8 warps (4M x 2N,
// warp tile 32x32), grid 8x16 = 128 CTAs (chip-filling vs 64 before).
// W half-tiles (64 rows) are contiguous 8 KB blocks of the 128-row tiles
// (rows are major within a tile; the swizzle depends only on row&7).
// ---------------------------------------------------------------------------
__global__ void __launch_bounds__(256, 1)
proj_mma(const char* __restrict__ Fh, const char* __restrict__ Fl,
         const char* __restrict__ Wh, const char* __restrict__ Wl,
         const float* __restrict__ bias, float* __restrict__ P)
{
    extern __shared__ char smem_raw[];
    const uint32_t sbase = sm_u32(smem_raw);
    const uint32_t mbar0 = sbase;
    const uint32_t data0 = (sbase + 32u + 1023u) & ~1023u;

    const int tid = threadIdx.x;
    const int w = tid >> 5, l = tid & 31;
    const int wm = w & 3;         // 4 M blocks of 32
    const int wn = w >> 2;        // 2 N blocks of 32
    const int mb = blockIdx.x;    // 0..7
    const int nb = blockIdx.y;    // 0..15  (64-wide N blocks)

    if (tid == 0) {
#pragma unroll
        for (int s = 0; s < NSTAGES_P; ++s)
            asm volatile("mbarrier.init.shared.b64 [%0], 1;" :: "r"(mbar0 + s * 8) : "memory");
    }
    __syncthreads();

    const int rowA  = wm * 32 + (l & 15);
    const uint32_t hA = (uint32_t)(l >> 4) << 4;
    const int rowB0 = wn * 32 + (l & 7) + ((l & 16) >> 1);   // 0..63 in half tile
    const uint32_t hB = (uint32_t)(l & 8) << 1;
    const uint32_t swz = (uint32_t)(l & 7) << 4;

    float    acc[2][2][2][4];     // [mi][nk][hf]
    uint32_t accC[2][2][2][2];
#pragma unroll
    for (int i = 0; i < 2; ++i)
#pragma unroll
        for (int j = 0; j < 2; ++j)
#pragma unroll
            for (int f = 0; f < 2; ++f) {
#pragma unroll
                for (int q = 0; q < 4; ++q) acc[i][j][f][q] = 0.f;
                accC[i][j][f][0] = 0u; accC[i][j][f][1] = 0u;
            }

    auto issue = [&](int kc, int s) {
        const uint32_t d = data0 + s * STAGE_P;
        const uint32_t bar = mbar0 + s * 8;
        const size_t aoff = ((size_t)mb * KCHUNKS + kc) * TILE_B;
        const size_t boff = ((size_t)(nb >> 1) * KCHUNKS + kc) * TILE_B
                          + (size_t)(nb & 1) * HTILE_B;
        asm volatile("mbarrier.arrive.expect_tx.shared.b64 _, [%0], %1;"
                     :: "r"(bar), "r"((uint32_t)STAGE_P) : "memory");
        BULK_LOAD(d,              Fh + aoff, bar);
        BULK_LOAD(d + 1 * TILE_B, Fl + aoff, bar);
        BULK_LOAD_SZ(d + 2 * TILE_B,           Wh + boff, bar, HTILE_B);
        BULK_LOAD_SZ(d + 2 * TILE_B + HTILE_B, Wl + boff, bar, HTILE_B);
    };

    if (tid == 0) { issue(0, 0); issue(1, 1); }

    int ph[NSTAGES_P] = {0, 0, 0};

    for (int kc = 0; kc < KCHUNKS; ++kc) {
        const int s = kc % NSTAGES_P;
        mbar_wait(mbar0 + s * 8, ph[s]);
        ph[s] ^= 1;
        __syncthreads();
        if (tid == 0 && kc + 2 < KCHUNKS) issue(kc + 2, (kc + 2) % NSTAGES_P);

        const uint32_t aHb = data0 + s * STAGE_P;
        const uint32_t aLb = aHb + 1 * TILE_B;
        const uint32_t bHb = aHb + 2 * TILE_B;
        const uint32_t bLb = bHb + HTILE_B;

#pragma unroll
        for (int ks = 0; ks < 4; ++ks) {
            uint32_t ah[2][4], al[2][4];
#pragma unroll
            for (int mi = 0; mi < 2; ++mi) {
                const uint32_t pa =
                    ((uint32_t)((rowA + mi * 16) * 128) + (uint32_t)(ks * 32) + hA) ^ swz;
                LDSM4(ah[mi], aHb + pa);
                LDSM4(al[mi], aLb + pa);
            }
#pragma unroll
            for (int nk = 0; nk < 2; ++nk) {
                const uint32_t pb =
                    ((uint32_t)((rowB0 + nk * 16) * 128) + (uint32_t)(ks * 32) + hB) ^ swz;
                uint32_t bh[4], bl[4];
                LDSM4(bh, bHb + pb);
                LDSM4(bl, bLb + pb);
#pragma unroll
                for (int mi = 0; mi < 2; ++mi) {
                    MMA_F16_F32(acc[mi][nk][0], ah[mi], bh[0], bh[1]);
                    MMA_F16_F32(acc[mi][nk][1], ah[mi], bh[2], bh[3]);
                    MMA_F16_F16(accC[mi][nk][0], ah[mi], bl[0], bl[1]);
                    MMA_F16_F16(accC[mi][nk][1], ah[mi], bl[2], bl[3]);
                    MMA_F16_F16(accC[mi][nk][0], al[mi], bh[0], bh[1]);
                    MMA_F16_F16(accC[mi][nk][1], al[mi], bh[2], bh[3]);
                }
            }
        }
    }

    const float cs = 1.0f / LO_SCALE;
    const int gm0 = mb * 128 + wm * 32 + (l >> 2);
    const int gn0 = nb * 64 + wn * 32 + (l & 3) * 2;
#pragma unroll
    for (int mi = 0; mi < 2; ++mi) {
#pragma unroll
        for (int nk = 0; nk < 2; ++nk) {
#pragma unroll
            for (int hf = 0; hf < 2; ++hf) {
                const int n = gn0 + nk * 16 + hf * 8;
                const float b0 = bias[n], b1 = bias[n + 1];
                const float* a = acc[mi][nk][hf];
                const uint32_t* c = accC[mi][nk][hf];
                const __half2 c0 = *(const __half2*)&c[0];
                const __half2 c1 = *(const __half2*)&c[1];
                float* p = P + (size_t)(gm0 + mi * 16) * FDIM + n;
                float2 v0, v1;
                v0.x = a[0] + __half2float(__low2half(c0))  * cs + b0;
                v0.y = a[1] + __half2float(__high2half(c0)) * cs + b1;
                v1.x = a[2] + __half2float(__low2half(c1))  * cs + b0;
                v1.y = a[3] + __half2float(__high2half(c1)) * cs + b1;
                *(float2*)p = v0;
                *(float2*)(p + (size_t)8 * FDIM) = v1;
            }
        }
    }
}

// ---------------------------------------------------------------------------
// Similarity GEMM slice (one mb block of 128 rows), single-term fp16
// (f32 accum). CTA tile 128x256, 16 warps. Async full/cons mbarrier pipeline,
// 4 stages x 48 KB. Grid (1, 128); mb passed as an argument.
// ---------------------------------------------------------------------------
__global__ void __launch_bounds__(512, 1)
sim_mma(const char* __restrict__ Ah, const char* __restrict__ Bh,
        float* __restrict__ S, int mb)
{
    extern __shared__ char smem_raw[];
    const uint32_t sbase = sm_u32(smem_raw);
    const uint32_t full0 = sbase;            // 4 x 8B
    const uint32_t cons0 = sbase + 32;       // 4 x 8B
    const uint32_t data0 = (sbase + 64u + 1023u) & ~1023u;

    const int tid = threadIdx.x;
    const int w = tid >> 5, l = tid & 31;
    const int wm = w & 3;
    const int wn = w >> 2;
    const int nb = blockIdx.y;    // 0..127

    if (tid == 0) {
#pragma unroll
        for (int s = 0; s < NSTAGES_S; ++s) {
            asm volatile("mbarrier.init.shared.b64 [%0], 1;"   :: "r"(full0 + s * 8) : "memory");
            asm volatile("mbarrier.init.shared.b64 [%0], 512;" :: "r"(cons0 + s * 8) : "memory");
        }
    }
    __syncthreads();

    const int rowA  = wm * 32 + (l & 15);
    const uint32_t hA = (uint32_t)(l >> 4) << 4;
    const int rowB0 = (wn & 1) * 64 + (l & 7) + ((l & 16) >> 1);
    const uint32_t hB = (uint32_t)(l & 8) << 1;
    const uint32_t swz = (uint32_t)(l & 7) << 4;
    const uint32_t bsel = (uint32_t)(wn >> 1) * TILE_B;

    float acc[2][8][4];
#pragma unroll
    for (int i = 0; i < 2; ++i)
#pragma unroll
        for (int j = 0; j < 8; ++j)
#pragma unroll
            for (int q = 0; q < 4; ++q) acc[i][j][q] = 0.f;

    auto issue = [&](int kc, int s) {
        const uint32_t d = data0 + s * STAGE_S;
        const uint32_t bar = full0 + s * 8;
        const size_t aoff  = ((size_t)mb * KCHUNKS + kc) * TILE_B;
        const size_t boff0 = ((size_t)(nb * 2 + 0) * KCHUNKS + kc) * TILE_B;
        const size_t boff1 = ((size_t)(nb * 2 + 1) * KCHUNKS + kc) * TILE_B;
        asm volatile("mbarrier.arrive.expect_tx.shared.b64 _, [%0], %1;"
                     :: "r"(bar), "r"((uint32_t)STAGE_S) : "memory");
        BULK_LOAD(d,              Ah + aoff,  bar);
        BULK_LOAD(d + 1 * TILE_B, Bh + boff0, bar);
        BULK_LOAD(d + 2 * TILE_B, Bh + boff1, bar);
    };

    if (tid == 0) { issue(0, 0); issue(1, 1); issue(2, 2); }

    int phf[NSTAGES_S] = {0, 0, 0, 0};
    int phc[NSTAGES_S] = {0, 0, 0, 0};   // used by tid 0 only

    for (int kc = 0; kc < KCHUNKS; ++kc) {
        const int s = kc & 3;
        mbar_wait(full0 + s * 8, phf[s]);
        phf[s] ^= 1;

        const uint32_t aHb = data0 + s * STAGE_S;
        const uint32_t bHb = aHb + TILE_B + bsel;

#pragma unroll
        for (int ks = 0; ks < 4; ++ks) {
            uint32_t ah[2][4];
#pragma unroll
            for (int mi = 0; mi < 2; ++mi) {
                const uint32_t pa =
                    ((uint32_t)((rowA + mi * 16) * 128) + (uint32_t)(ks * 32) + hA) ^ swz;
                LDSM4(ah[mi], aHb + pa);
            }
#pragma unroll
            for (int nk = 0; nk < 4; ++nk) {
                const uint32_t pb =
                    ((uint32_t)((rowB0 + nk * 16) * 128) + (uint32_t)(ks * 32) + hB) ^ swz;
                uint32_t bh[4];
                LDSM4(bh, bHb + pb);
#pragma unroll
                for (int mi = 0; mi < 2; ++mi) {
                    MMA_F16_F32(acc[mi][nk * 2 + 0], ah[mi], bh[0], bh[1]);
                    MMA_F16_F32(acc[mi][nk * 2 + 1], ah[mi], bh[2], bh[3]);
                }
            }
        }

        MBAR_ARRIVE(cons0 + s * 8);

        if (tid == 0 && kc + 3 < KCHUNKS) {
            const int s2 = (kc + 3) & 3;
            if (kc >= 1) {
                mbar_wait(cons0 + s2 * 8, phc[s2]);
                phc[s2] ^= 1;
            }
            issue(kc + 3, s2);
        }
    }

    const int gm0 = mb * 128 + wm * 32 + (l >> 2);
    const int gn0 = nb * 256 + wn * 64 + (l & 3) * 2;
#pragma unroll
    for (int mi = 0; mi < 2; ++mi) {
#pragma unroll
        for (int nk = 0; nk < 4; ++nk) {
#pragma unroll
            for (int hf = 0; hf < 2; ++hf) {
                const float* a = acc[mi][nk * 2 + hf];
                float* p = S + (size_t)(gm0 + mi * 16) * NCONCEPT + gn0 + nk * 16 + hf * 8;
                float2 v0, v1;
                v0.x = a[0]; v0.y = a[1];
                v1.x = a[2]; v1.y = a[3];
                *(float2*)p = v0;
                *(float2*)(p + (size_t)8 * NCONCEPT) = v1;
            }
        }
    }
}

// ---------------------------------------------------------------------------
// Per-row softmax(sim * INV_T) + argmax, row staged in SMEM (single S read).
// One CTA (512 threads) per row; 128 KB dynamic smem. row = row_base + blockIdx.x.
// ---------------------------------------------------------------------------
__global__ void __launch_bounds__(512)
softmax_row(const float* __restrict__ S,
            float* __restrict__ act,
            float* __restrict__ bidx,
            int row_base)
{
    extern __shared__ float srow[];
    const int row = row_base + blockIdx.x;
    const int tid = threadIdx.x;
    const float4* s4 = (const float4*)(S + (size_t)row * NCONCEPT);
    float4* r4 = (float4*)srow;

    float m = -INFINITY;
    float Z = 0.f;
    int   bi = 0;

    for (int j = tid; j < NCONCEPT / 4; j += 512) {
        const float4 v = s4[j];
        r4[j] = v;
        const float x[4] = {v.x, v.y, v.z, v.w};
#pragma unroll
        for (int q = 0; q < 4; ++q) {
            if (x[q] > m) {
                Z = Z * __expf((m - x[q]) * INV_T) + 1.0f;
                m = x[q];
                bi = j * 4 + q;
            } else {
                Z += __expf((x[q] - m) * INV_T);
            }
        }
    }

    __shared__ float sm[512];
    __shared__ float sz[512];
    __shared__ int   si[512];
    sm[tid] = m; sz[tid] = Z; si[tid] = bi;
    __syncthreads();

#pragma unroll
    for (int off = 256; off > 0; off >>= 1) {
        if (tid < off) {
            const float m1 = sm[tid],       z1 = sz[tid];
            const float m2 = sm[tid + off], z2 = sz[tid + off];
            const int   i1 = si[tid],       i2 = si[tid + off];
            if (m2 > m1 || (m2 == m1 && i2 < i1)) {
                sm[tid] = m2;
                sz[tid] = z2 + z1 * __expf((m1 - m2) * INV_T);
                si[tid] = i2;
            } else {
                sz[tid] = z1 + z2 * __expf((m2 - m1) * INV_T);
            }
        }
        __syncthreads();
    }

    const float M    = sm[0];
    const float invZ = 1.0f / sz[0];
    float4* a4 = (float4*)(act + (size_t)row * NCONCEPT);
    for (int j = tid; j < NCONCEPT / 4; j += 512) {
        const float4 v = r4[j];
        float4 o;
        o.x = __expf((v.x - M) * INV_T) * invZ;
        o.y = __expf((v.y - M) * INV_T) * invZ;
        o.z = __expf((v.z - M) * INV_T) * invZ;
        o.w = __expf((v.w - M) * INV_T) * invZ;
        a4[j] = o;
    }

    if (tid == 0) bidx[row] = (float)si[0];
}

// ---------------------------------------------------------------------------
extern "C" void kernel_launch(void* const* d_in, const int* in_sizes, int n_in,
                              void* d_out, int out_size)
{
    const float* features   = (const float*)d_in[0];  // [1024, 1024]
    const float* W          = (const float*)d_in[1];  // [1024, 1024]
    const float* b          = (const float*)d_in[2];  // [1024]
    const float* prototypes = (const float*)d_in[3];  // [32768, 1024]

    float* out  = (float*)d_out;
    float* act  = out;                                   // [1024, 32768]
    float* bidx = out + (size_t)BATCH * NCONCEPT;        // [1024] as float

    float *pP = nullptr, *pS = nullptr;
    char *pFh = nullptr, *pFl = nullptr, *pWh = nullptr, *pWl = nullptr;
    char *pAh = nullptr, *pBh = nullptr;
    cudaGetSymbolAddress((void**)&pP,  g_P);
    cudaGetSymbolAddress((void**)&pS,  g_S);
    cudaGetSymbolAddress((void**)&pFh, g_Fh);
    cudaGetSymbolAddress((void**)&pFl, g_Fl);
    cudaGetSymbolAddress((void**)&pWh, g_Wh);
    cudaGetSymbolAddress((void**)&pWl, g_Wl);
    cudaGetSymbolAddress((void**)&pAh, g_Ah);
    cudaGetSymbolAddress((void**)&pBh, g_Bh);

    cudaFuncSetAttribute(proj_mma, cudaFuncAttributeMaxDynamicSharedMemorySize, SMEM_PROJ);
    cudaFuncSetAttribute(sim_mma,  cudaFuncAttributeMaxDynamicSharedMemorySize, SMEM_SIM);
    cudaFuncSetAttribute(softmax_row, cudaFuncAttributeMaxDynamicSharedMemorySize, SMEM_SOFT);

    // ONE extra stream + four events (budget proven delta=0 in R13/R15).
    cudaStream_t sB = nullptr;
    cudaEvent_t evFork = nullptr, evA = nullptr, evB = nullptr, evJoin = nullptr;
    cudaStreamCreateWithFlags(&sB, cudaStreamNonBlocking);
    cudaEventCreateWithFlags(&evFork, cudaEventDisableTiming);
    cudaEventCreateWithFlags(&evA, cudaEventDisableTiming);
    cudaEventCreateWithFlags(&evB, cudaEventDisableTiming);
    cudaEventCreateWithFlags(&evJoin, cudaEventDisableTiming);

    // Fork: convert_b on sB in parallel with the projection chain.
    cudaEventRecord(evFork, 0);
    cudaStreamWaitEvent(sB, evFork, 0);
    convert_b<<<(NCONCEPT * FDIM / 4) / 256, 256, 0, sB>>>(
        (const float4*)prototypes, pBh);
    cudaEventRecord(evB, sB);

    // Projection chain on the default stream (proj now grid 8x16 = 128 CTAs):
    convert_split2<<<(BATCH * FDIM / 4) / 256, 256>>>((const float4*)features, pFh, pFl);
    convert_split2<<<(FDIM * FDIM / 4) / 256, 256>>>((const float4*)W, pWh, pWl);
    proj_mma<<<dim3(BATCH / 128, FDIM / 64), 256, SMEM_PROJ>>>(
        pFh, pFl, pWh, pWl, b, pP);
    convert_a<<<BATCH, 256>>>((const float4*)pP, pAh);
    cudaEventRecord(evA, 0);

    // Cross deps: default stream needs Bh; sB needs Ah.
    cudaStreamWaitEvent(0, evB, 0);
    cudaStreamWaitEvent(sB, evA, 0);

    // Interleaved sim/softmax slices across the two streams.
    for (int i = 0; i < NSLICES; ++i) {
        cudaStream_t s = (i & 1) ? sB : (cudaStream_t)0;
        sim_mma<<<dim3(1, NCONCEPT / 256), 512, SMEM_SIM, s>>>(pAh, pBh, pS, i);
        softmax_row<<<BATCH / NSLICES, 512, SMEM_SOFT, s>>>(pS, act, bidx, i * 128);
    }

    // Join sB back into the default stream.
    cudaEventRecord(evJoin, sB);
    cudaStreamWaitEvent(0, evJoin, 0);
}

// round 17
// speedup vs baseline: 1.2439x; 1.0397x over previous
#include <cuda_runtime.h>
#include <cuda_fp16.h>
#include <math.h>
#include <stdint.h>

// Problem constants
#define BATCH     1024
#define FDIM      1024
#define NCONCEPT  32768
#define INV_T     10.0f   // 1 / 0.1

#define TILE_B    16384          // one 128x64-fp16 swizzled tile (128 rows * 128 B)
#define HTILE_B   8192           // half tile: 64 rows (contiguous within a tile)
#define KCHUNKS   16             // 1024 / 64
#define LO_SCALE  2048.0f        // 2^11

// sim pipeline: A (1 tile) + B (2 tiles) per stage = 48 KB, 4 stages (async)
#define STAGE_S   (3 * TILE_B)
#define NSTAGES_S 4
#define SMEM_SIM  (1024 + NSTAGES_S * STAGE_S)
// proj pipeline: Fh+Fl tiles + Wh+Wl half-tiles = 48 KB, 3 stages
#define STAGE_P   (2 * TILE_B + 2 * HTILE_B)
#define NSTAGES_P 3
#define SMEM_PROJ (1024 + NSTAGES_P * STAGE_P)

#define NSLICES   8              // mb slices for sim/softmax overlap

// ---------------- scratch (device globals; no allocation allowed) ----------
__device__ float g_P[BATCH * FDIM];
__device__ float g_S[(size_t)BATCH * NCONCEPT];          // similarities (134 MB)
__device__ __align__(256) char g_Fh[(size_t)BATCH * FDIM * 2];
__device__ __align__(256) char g_Fl[(size_t)BATCH * FDIM * 2];
__device__ __align__(256) char g_Wh[(size_t)FDIM * FDIM * 2];
__device__ __align__(256) char g_Wl[(size_t)FDIM * FDIM * 2];
__device__ __align__(256) char g_Ah[(size_t)BATCH * FDIM * 2];
__device__ __align__(256) char g_Bh[(size_t)NCONCEPT * FDIM * 2];

// ---------------------------------------------------------------------------
// PTX helpers (baseline ISA only)
// ---------------------------------------------------------------------------
__device__ __forceinline__ uint32_t sm_u32(const void* p) {
    uint32_t a;
    asm("{ .reg .u64 t; cvta.to.shared.u64 t, %1; cvt.u32.u64 %0, t; }"
        : "=r"(a) : "l"(p));
    return a;
}

__device__ __forceinline__ void mbar_wait(uint32_t addr, int phase) {
    asm volatile(
        "{\n\t.reg .pred P;\n\t"
        "WL_%=:\n\t"
        "mbarrier.try_wait.parity.acquire.cta.shared::cta.b64 P, [%0], %1, 0x989680;\n\t"
        "@P bra.uni WD_%=;\n\t"
        "bra.uni WL_%=;\n\t"
        "WD_%=:\n\t}"
        :: "r"(addr), "r"((uint32_t)phase) : "memory");
}

#define MBAR_ARRIVE(addr) \
    asm volatile("mbarrier.arrive.shared.b64 _, [%0];" :: "r"(addr) : "memory")

#define LDSM4(R, addr) \
    asm volatile("ldmatrix.sync.aligned.m8n8.x4.shared.b16 {%0,%1,%2,%3}, [%4];" \
        : "=r"((R)[0]), "=r"((R)[1]), "=r"((R)[2]), "=r"((R)[3]) : "r"(addr))

#define MMA_F16_F32(C, A, b0_, b1_) \
    asm volatile("mma.sync.aligned.m16n8k16.row.col.f32.f16.f16.f32 " \
        "{%0,%1,%2,%3}, {%4,%5,%6,%7}, {%8,%9}, {%0,%1,%2,%3};" \
        : "+f"((C)[0]), "+f"((C)[1]), "+f"((C)[2]), "+f"((C)[3]) \
        : "r"((A)[0]), "r"((A)[1]), "r"((A)[2]), "r"((A)[3]), "r"(b0_), "r"(b1_))

#define MMA_F16_F16(C, A, b0_, b1_) \
    asm volatile("mma.sync.aligned.m16n8k16.row.col.f16.f16.f16.f16 " \
        "{%0,%1}, {%2,%3,%4,%5}, {%6,%7}, {%0,%1};" \
        : "+r"((C)[0]), "+r"((C)[1]) \
        : "r"((A)[0]), "r"((A)[1]), "r"((A)[2]), "r"((A)[3]), "r"(b0_), "r"(b1_))

#define BULK_LOAD(dst, src, bar) \
    asm volatile("cp.async.bulk.shared::cluster.global.mbarrier::complete_tx::bytes " \
        "[%0], [%1], %2, [%3];" \
        :: "r"(dst), "l"(src), "r"((uint32_t)TILE_B), "r"(bar) : "memory")

#define BULK_LOAD_SZ(dst, src, bar, sz) \
    asm volatile("cp.async.bulk.shared::cluster.global.mbarrier::complete_tx::bytes " \
        "[%0], [%1], %2, [%3];" \
        :: "r"(dst), "l"(src), "r"((uint32_t)(sz)), "r"(bar) : "memory")

// ---------------------------------------------------------------------------
// fp32 -> fp16 two-limb split into pre-swizzled 128x64 tiles: F and W in one
// launch (rows 0..1023 = F, 1024..2047 = W).
// ---------------------------------------------------------------------------
__global__ void __launch_bounds__(256)
convert_split_dual(const float4* __restrict__ srcF, const float4* __restrict__ srcW,
                   char* __restrict__ Fh, char* __restrict__ Fl,
                   char* __restrict__ Wh, char* __restrict__ Wl)
{
    const size_t i4 = (size_t)blockIdx.x * 256 + threadIdx.x;
    int row = (int)(i4 >> 8);
    const int k = ((int)i4 & 255) * 4;

    const float4* src;
    char *hi, *lo;
    if (row < BATCH) {
        src = srcF; hi = Fh; lo = Fl;
    } else {
        src = srcW + (size_t)(BATCH) * 256 - (size_t)BATCH * 256;  // base stays srcW
        src = srcW; hi = Wh; lo = Wl; row -= BATCH;
    }
    const float4 v = src[(size_t)row * 256 + (k >> 2)];
    const float x[4] = {v.x, v.y, v.z, v.w};

    unsigned short h[4], l[4];
#pragma unroll
    for (int j = 0; j < 4; ++j) {
        const __half hb = __float2half_rn(x[j]);
        const float r = (x[j] - __half2float(hb)) * LO_SCALE;
        h[j] = __half_as_ushort(hb);
        l[j] = __half_as_ushort(__float2half_rn(r));
    }

    const int tile = (row >> 7) * KCHUNKS + (k >> 6);
    uint32_t off = (uint32_t)((row & 127) * 128 + (k & 63) * 2);
    off ^= (off >> 3) & 0x70;

    uint2 ph, pl;
    ph.x = (uint32_t)h[0] | ((uint32_t)h[1] << 16);
    ph.y = (uint32_t)h[2] | ((uint32_t)h[3] << 16);
    pl.x = (uint32_t)l[0] | ((uint32_t)l[1] << 16);
    pl.y = (uint32_t)l[2] | ((uint32_t)l[3] << 16);
    *(uint2*)(hi + (size_t)tile * TILE_B + off) = ph;
    *(uint2*)(lo + (size_t)tile * TILE_B + off) = pl;
}

// ---------------------------------------------------------------------------
// A-side: fused L2-normalize + fp16 hi limb only. One CTA per row.
// ---------------------------------------------------------------------------
__global__ void __launch_bounds__(256)
convert_a(const float4* __restrict__ src, char* __restrict__ hi)
{
    const int row = blockIdx.x;
    const int tid = threadIdx.x;
    const float4 v = src[(size_t)row * 256 + tid];
    const float x[4] = {v.x, v.y, v.z, v.w};

    __shared__ float red[256];
    red[tid] = x[0]*x[0] + x[1]*x[1] + x[2]*x[2] + x[3]*x[3];
    __syncthreads();
#pragma unroll
    for (int off = 128; off > 0; off >>= 1) {
        if (tid < off) red[tid] += red[tid + off];
        __syncthreads();
    }
    const float inv = 1.0f / fmaxf(sqrtf(red[0]), 1e-12f);

    unsigned short h[4];
#pragma unroll
    for (int j = 0; j < 4; ++j)
        h[j] = __half_as_ushort(__float2half_rn(x[j] * inv));

    const int k = tid * 4;
    const int tile = (row >> 7) * KCHUNKS + (k >> 6);
    uint32_t off = (uint32_t)((row & 127) * 128 + (k & 63) * 2);
    off ^= (off >> 3) & 0x70;

    uint2 ph;
    ph.x = (uint32_t)h[0] | ((uint32_t)h[1] << 16);
    ph.y = (uint32_t)h[2] | ((uint32_t)h[3] << 16);
    *(uint2*)(hi + (size_t)tile * TILE_B + off) = ph;
}

// ---------------------------------------------------------------------------
// B-side: fp16 hi limb only, pre-swizzled tiles.
// ---------------------------------------------------------------------------
__global__ void __launch_bounds__(256)
convert_b(const float4* __restrict__ src, char* __restrict__ hi)
{
    const size_t i4 = (size_t)blockIdx.x * 256 + threadIdx.x;
    const int row = (int)(i4 >> 8);
    const int k   = ((int)i4 & 255) * 4;
    const float4 v = src[i4];
    const float x[4] = {v.x, v.y, v.z, v.w};

    unsigned short h[4];
#pragma unroll
    for (int j = 0; j < 4; ++j)
        h[j] = __half_as_ushort(__float2half_rn(x[j]));

    const int tile = (row >> 7) * KCHUNKS + (k >> 6);
    uint32_t off = (uint32_t)((row & 127) * 128 + (k & 63) * 2);
    off ^= (off >> 3) & 0x70;

    uint2 ph;
    ph.x = (uint32_t)h[0] | ((uint32_t)h[1] << 16);
    ph.y = (uint32_t)h[2] | ((uint32_t)h[3] << 16);
    *(uint2*)(hi + (size_t)tile * TILE_B + off) = ph;
}

// ---------------------------------------------------------------------------
// Projection GEMM, fp16 3-term limbs (~fp32). CTA 128x64, 8 warps (4M x 2N,
// warp tile 32x32), grid 8x16 = 128 CTAs.
// ---------------------------------------------------------------------------
__global__ void __launch_bounds__(256, 1)
proj_mma(const char* __restrict__ Fh, const char* __restrict__ Fl,
         const char* __restrict__ Wh, const char* __restrict__ Wl,
         const float* __restrict__ bias, float* __restrict__ P)
{
    extern __shared__ char smem_raw[];
    const uint32_t sbase = sm_u32(smem_raw);
    const uint32_t mbar0 = sbase;
    const uint32_t data0 = (sbase + 32u + 1023u) & ~1023u;

    const int tid = threadIdx.x;
    const int w = tid >> 5, l = tid & 31;
    const int wm = w & 3;
    const int wn = w >> 2;
    const int mb = blockIdx.x;    // 0..7
    const int nb = blockIdx.y;    // 0..15

    if (tid == 0) {
#pragma unroll
        for (int s = 0; s < NSTAGES_P; ++s)
            asm volatile("mbarrier.init.shared.b64 [%0], 1;" :: "r"(mbar0 + s * 8) : "memory");
    }
    __syncthreads();

    const int rowA  = wm * 32 + (l & 15);
    const uint32_t hA = (uint32_t)(l >> 4) << 4;
    const int rowB0 = wn * 32 + (l & 7) + ((l & 16) >> 1);
    const uint32_t hB = (uint32_t)(l & 8) << 1;
    const uint32_t swz = (uint32_t)(l & 7) << 4;

    float    acc[2][2][2][4];
    uint32_t accC[2][2][2][2];
#pragma unroll
    for (int i = 0; i < 2; ++i)
#pragma unroll
        for (int j = 0; j < 2; ++j)
#pragma unroll
            for (int f = 0; f < 2; ++f) {
#pragma unroll
                for (int q = 0; q < 4; ++q) acc[i][j][f][q] = 0.f;
                accC[i][j][f][0] = 0u; accC[i][j][f][1] = 0u;
            }

    auto issue = [&](int kc, int s) {
        const uint32_t d = data0 + s * STAGE_P;
        const uint32_t bar = mbar0 + s * 8;
        const size_t aoff = ((size_t)mb * KCHUNKS + kc) * TILE_B;
        const size_t boff = ((size_t)(nb >> 1) * KCHUNKS + kc) * TILE_B
                          + (size_t)(nb & 1) * HTILE_B;
        asm volatile("mbarrier.arrive.expect_tx.shared.b64 _, [%0], %1;"
                     :: "r"(bar), "r"((uint32_t)STAGE_P) : "memory");
        BULK_LOAD(d,              Fh + aoff, bar);
        BULK_LOAD(d + 1 * TILE_B, Fl + aoff, bar);
        BULK_LOAD_SZ(d + 2 * TILE_B,           Wh + boff, bar, HTILE_B);
        BULK_LOAD_SZ(d + 2 * TILE_B + HTILE_B, Wl + boff, bar, HTILE_B);
    };

    if (tid == 0) { issue(0, 0); issue(1, 1); }

    int ph[NSTAGES_P] = {0, 0, 0};

    for (int kc = 0; kc < KCHUNKS; ++kc) {
        const int s = kc % NSTAGES_P;
        mbar_wait(mbar0 + s * 8, ph[s]);
        ph[s] ^= 1;
        __syncthreads();
        if (tid == 0 && kc + 2 < KCHUNKS) issue(kc + 2, (kc + 2) % NSTAGES_P);

        const uint32_t aHb = data0 + s * STAGE_P;
        const uint32_t aLb = aHb + 1 * TILE_B;
        const uint32_t bHb = aHb + 2 * TILE_B;
        const uint32_t bLb = bHb + HTILE_B;

#pragma unroll
        for (int ks = 0; ks < 4; ++ks) {
            uint32_t ah[2][4], al[2][4];
#pragma unroll
            for (int mi = 0; mi < 2; ++mi) {
                const uint32_t pa =
                    ((uint32_t)((rowA + mi * 16) * 128) + (uint32_t)(ks * 32) + hA) ^ swz;
                LDSM4(ah[mi], aHb + pa);
                LDSM4(al[mi], aLb + pa);
            }
#pragma unroll
            for (int nk = 0; nk < 2; ++nk) {
                const uint32_t pb =
                    ((uint32_t)((rowB0 + nk * 16) * 128) + (uint32_t)(ks * 32) + hB) ^ swz;
                uint32_t bh[4], bl[4];
                LDSM4(bh, bHb + pb);
                LDSM4(bl, bLb + pb);
#pragma unroll
                for (int mi = 0; mi < 2; ++mi) {
                    MMA_F16_F32(acc[mi][nk][0], ah[mi], bh[0], bh[1]);
                    MMA_F16_F32(acc[mi][nk][1], ah[mi], bh[2], bh[3]);
                    MMA_F16_F16(accC[mi][nk][0], ah[mi], bl[0], bl[1]);
                    MMA_F16_F16(accC[mi][nk][1], ah[mi], bl[2], bl[3]);
                    MMA_F16_F16(accC[mi][nk][0], al[mi], bh[0], bh[1]);
                    MMA_F16_F16(accC[mi][nk][1], al[mi], bh[2], bh[3]);
                }
            }
        }
    }

    const float cs = 1.0f / LO_SCALE;
    const int gm0 = mb * 128 + wm * 32 + (l >> 2);
    const int gn0 = nb * 64 + wn * 32 + (l & 3) * 2;
#pragma unroll
    for (int mi = 0; mi < 2; ++mi) {
#pragma unroll
        for (int nk = 0; nk < 2; ++nk) {
#pragma unroll
            for (int hf = 0; hf < 2; ++hf) {
                const int n = gn0 + nk * 16 + hf * 8;
                const float b0 = bias[n], b1 = bias[n + 1];
                const float* a = acc[mi][nk][hf];
                const uint32_t* c = accC[mi][nk][hf];
                const __half2 c0 = *(const __half2*)&c[0];
                const __half2 c1 = *(const __half2*)&c[1];
                float* p = P + (size_t)(gm0 + mi * 16) * FDIM + n;
                float2 v0, v1;
                v0.x = a[0] + __half2float(__low2half(c0))  * cs + b0;
                v0.y = a[1] + __half2float(__high2half(c0)) * cs + b1;
                v1.x = a[2] + __half2float(__low2half(c1))  * cs + b0;
                v1.y = a[3] + __half2float(__high2half(c1)) * cs + b1;
                *(float2*)p = v0;
                *(float2*)(p + (size_t)8 * FDIM) = v1;
            }
        }
    }
}

// ---------------------------------------------------------------------------
// Similarity GEMM slice (one mb block of 128 rows), single-term fp16
// (f32 accum). CTA tile 128x256, 16 warps. Async full/cons mbarrier pipeline,
// 4 stages x 48 KB. Grid (1, 128); mb passed as an argument.
// ---------------------------------------------------------------------------
__global__ void __launch_bounds__(512, 1)
sim_mma(const char* __restrict__ Ah, const char* __restrict__ Bh,
        float* __restrict__ S, int mb)
{
    extern __shared__ char smem_raw[];
    const uint32_t sbase = sm_u32(smem_raw);
    const uint32_t full0 = sbase;            // 4 x 8B
    const uint32_t cons0 = sbase + 32;       // 4 x 8B
    const uint32_t data0 = (sbase + 64u + 1023u) & ~1023u;

    const int tid = threadIdx.x;
    const int w = tid >> 5, l = tid & 31;
    const int wm = w & 3;
    const int wn = w >> 2;
    const int nb = blockIdx.y;    // 0..127

    if (tid == 0) {
#pragma unroll
        for (int s = 0; s < NSTAGES_S; ++s) {
            asm volatile("mbarrier.init.shared.b64 [%0], 1;"   :: "r"(full0 + s * 8) : "memory");
            asm volatile("mbarrier.init.shared.b64 [%0], 512;" :: "r"(cons0 + s * 8) : "memory");
        }
    }
    __syncthreads();

    const int rowA  = wm * 32 + (l & 15);
    const uint32_t hA = (uint32_t)(l >> 4) << 4;
    const int rowB0 = (wn & 1) * 64 + (l & 7) + ((l & 16) >> 1);
    const uint32_t hB = (uint32_t)(l & 8) << 1;
    const uint32_t swz = (uint32_t)(l & 7) << 4;
    const uint32_t bsel = (uint32_t)(wn >> 1) * TILE_B;

    float acc[2][8][4];
#pragma unroll
    for (int i = 0; i < 2; ++i)
#pragma unroll
        for (int j = 0; j < 8; ++j)
#pragma unroll
            for (int q = 0; q < 4; ++q) acc[i][j][q] = 0.f;

    auto issue = [&](int kc, int s) {
        const uint32_t d = data0 + s * STAGE_S;
        const uint32_t bar = full0 + s * 8;
        const size_t aoff  = ((size_t)mb * KCHUNKS + kc) * TILE_B;
        const size_t boff0 = ((size_t)(nb * 2 + 0) * KCHUNKS + kc) * TILE_B;
        const size_t boff1 = ((size_t)(nb * 2 + 1) * KCHUNKS + kc) * TILE_B;
        asm volatile("mbarrier.arrive.expect_tx.shared.b64 _, [%0], %1;"
                     :: "r"(bar), "r"((uint32_t)STAGE_S) : "memory");
        BULK_LOAD(d,              Ah + aoff,  bar);
        BULK_LOAD(d + 1 * TILE_B, Bh + boff0, bar);
        BULK_LOAD(d + 2 * TILE_B, Bh + boff1, bar);
    };

    if (tid == 0) { issue(0, 0); issue(1, 1); issue(2, 2); }

    int phf[NSTAGES_S] = {0, 0, 0, 0};
    int phc[NSTAGES_S] = {0, 0, 0, 0};   // used by tid 0 only

    for (int kc = 0; kc < KCHUNKS; ++kc) {
        const int s = kc & 3;
        mbar_wait(full0 + s * 8, phf[s]);
        phf[s] ^= 1;

        const uint32_t aHb = data0 + s * STAGE_S;
        const uint32_t bHb = aHb + TILE_B + bsel;

#pragma unroll
        for (int ks = 0; ks < 4; ++ks) {
            uint32_t ah[2][4];
#pragma unroll
            for (int mi = 0; mi < 2; ++mi) {
                const uint32_t pa =
                    ((uint32_t)((rowA + mi * 16) * 128) + (uint32_t)(ks * 32) + hA) ^ swz;
                LDSM4(ah[mi], aHb + pa);
            }
#pragma unroll
            for (int nk = 0; nk < 4; ++nk) {
                const uint32_t pb =
                    ((uint32_t)((rowB0 + nk * 16) * 128) + (uint32_t)(ks * 32) + hB) ^ swz;
                uint32_t bh[4];
                LDSM4(bh, bHb + pb);
#pragma unroll
                for (int mi = 0; mi < 2; ++mi) {
                    MMA_F16_F32(acc[mi][nk * 2 + 0], ah[mi], bh[0], bh[1]);
                    MMA_F16_F32(acc[mi][nk * 2 + 1], ah[mi], bh[2], bh[3]);
                }
            }
        }

        MBAR_ARRIVE(cons0 + s * 8);

        if (tid == 0 && kc + 3 < KCHUNKS) {
            const int s2 = (kc + 3) & 3;
            if (kc >= 1) {
                mbar_wait(cons0 + s2 * 8, phc[s2]);
                phc[s2] ^= 1;
            }
            issue(kc + 3, s2);
        }
    }

    const int gm0 = mb * 128 + wm * 32 + (l >> 2);
    const int gn0 = nb * 256 + wn * 64 + (l & 3) * 2;
#pragma unroll
    for (int mi = 0; mi < 2; ++mi) {
#pragma unroll
        for (int nk = 0; nk < 4; ++nk) {
#pragma unroll
            for (int hf = 0; hf < 2; ++hf) {
                const float* a = acc[mi][nk * 2 + hf];
                float* p = S + (size_t)(gm0 + mi * 16) * NCONCEPT + gn0 + nk * 16 + hf * 8;
                float2 v0, v1;
                v0.x = a[0]; v0.y = a[1];
                v1.x = a[2]; v1.y = a[3];
                *(float2*)p = v0;
                *(float2*)(p + (size_t)8 * NCONCEPT) = v1;
            }
        }
    }
}

// ---------------------------------------------------------------------------
// Per-row softmax(sim * INV_T) + argmax, UNstaged (two L2-resident reads of
// the slice S chunk, which sim just wrote through L2). Tiny static SMEM so
// these CTAs co-reside with sim CTAs on the same SMs (true overlap).
// One CTA (512 threads) per row; row = row_base + blockIdx.x.
// ---------------------------------------------------------------------------
__global__ void __launch_bounds__(512)
softmax_row(const float* __restrict__ S,
            float* __restrict__ act,
            float* __restrict__ bidx,
            int row_base)
{
    const int row = row_base + blockIdx.x;
    const int tid = threadIdx.x;
    const float4* s4 = (const float4*)(S + (size_t)row * NCONCEPT);

    float m = -INFINITY;
    float Z = 0.f;
    int   bi = 0;

    for (int j = tid; j < NCONCEPT / 4; j += 512) {
        const float4 v = s4[j];
        const float x[4] = {v.x, v.y, v.z, v.w};
#pragma unroll
        for (int q = 0; q < 4; ++q) {
            if (x[q] > m) {
                Z = Z * __expf((m - x[q]) * INV_T) + 1.0f;
                m = x[q];
                bi = j * 4 + q;
            } else {
                Z += __expf((x[q] - m) * INV_T);
            }
        }
    }

    __shared__ float sm[512];
    __shared__ float sz[512];
    __shared__ int   si[512];
    sm[tid] = m; sz[tid] = Z; si[tid] = bi;
    __syncthreads();

#pragma unroll
    for (int off = 256; off > 0; off >>= 1) {
        if (tid < off) {
            const float m1 = sm[tid],       z1 = sz[tid];
            const float m2 = sm[tid + off], z2 = sz[tid + off];
            const int   i1 = si[tid],       i2 = si[tid + off];
            if (m2 > m1 || (m2 == m1 && i2 < i1)) {
                sm[tid] = m2;
                sz[tid] = z2 + z1 * __expf((m1 - m2) * INV_T);
                si[tid] = i2;
            } else {
                sz[tid] = z1 + z2 * __expf((m2 - m1) * INV_T);
            }
        }
        __syncthreads();
    }

    const float M    = sm[0];
    const float invZ = 1.0f / sz[0];
    float4* a4 = (float4*)(act + (size_t)row * NCONCEPT);
    for (int j = tid; j < NCONCEPT / 4; j += 512) {
        const float4 v = s4[j];
        float4 o;
        o.x = __expf((v.x - M) * INV_T) * invZ;
        o.y = __expf((v.y - M) * INV_T) * invZ;
        o.z = __expf((v.z - M) * INV_T) * invZ;
        o.w = __expf((v.w - M) * INV_T) * invZ;
        a4[j] = o;
    }

    if (tid == 0) bidx[row] = (float)si[0];
}

// ---------------------------------------------------------------------------
extern "C" void kernel_launch(void* const* d_in, const int* in_sizes, int n_in,
                              void* d_out, int out_size)
{
    const float* features   = (const float*)d_in[0];  // [1024, 1024]
    const float* W          = (const float*)d_in[1];  // [1024, 1024]
    const float* b          = (const float*)d_in[2];  // [1024]
    const float* prototypes = (const float*)d_in[3];  // [32768, 1024]

    float* out  = (float*)d_out;
    float* act  = out;                                   // [1024, 32768]
    float* bidx = out + (size_t)BATCH * NCONCEPT;        // [1024] as float

    float *pP = nullptr, *pS = nullptr;
    char *pFh = nullptr, *pFl = nullptr, *pWh = nullptr, *pWl = nullptr;
    char *pAh = nullptr, *pBh = nullptr;
    cudaGetSymbolAddress((void**)&pP,  g_P);
    cudaGetSymbolAddress((void**)&pS,  g_S);
    cudaGetSymbolAddress((void**)&pFh, g_Fh);
    cudaGetSymbolAddress((void**)&pFl, g_Fl);
    cudaGetSymbolAddress((void**)&pWh, g_Wh);
    cudaGetSymbolAddress((void**)&pWl, g_Wl);
    cudaGetSymbolAddress((void**)&pAh, g_Ah);
    cudaGetSymbolAddress((void**)&pBh, g_Bh);

    cudaFuncSetAttribute(proj_mma, cudaFuncAttributeMaxDynamicSharedMemorySize, SMEM_PROJ);
    cudaFuncSetAttribute(sim_mma,  cudaFuncAttributeMaxDynamicSharedMemorySize, SMEM_SIM);

    // ONE extra stream + four events (budget proven delta=0 in R13/R15/R16).
    cudaStream_t sB = nullptr;
    cudaEvent_t evFork = nullptr, evA = nullptr, evB = nullptr, evJoin = nullptr;
    cudaStreamCreateWithFlags(&sB, cudaStreamNonBlocking);
    cudaEventCreateWithFlags(&evFork, cudaEventDisableTiming);
    cudaEventCreateWithFlags(&evA, cudaEventDisableTiming);
    cudaEventCreateWithFlags(&evB, cudaEventDisableTiming);
    cudaEventCreateWithFlags(&evJoin, cudaEventDisableTiming);

    // Fork: convert_b on sB in parallel with the projection chain.
    cudaEventRecord(evFork, 0);
    cudaStreamWaitEvent(sB, evFork, 0);
    convert_b<<<(NCONCEPT * FDIM / 4) / 256, 256, 0, sB>>>(
        (const float4*)prototypes, pBh);
    cudaEventRecord(evB, sB);

    // Projection chain on the default stream:
    convert_split_dual<<<((BATCH + FDIM) * FDIM / 4) / 256, 256>>>(
        (const float4*)features, (const float4*)W, pFh, pFl, pWh, pWl);
    proj_mma<<<dim3(BATCH / 128, FDIM / 64), 256, SMEM_PROJ>>>(
        pFh, pFl, pWh, pWl, b, pP);
    convert_a<<<BATCH, 256>>>((const float4*)pP, pAh);
    cudaEventRecord(evA, 0);

    // Cross deps: default stream needs Bh; sB needs Ah.
    cudaStreamWaitEvent(0, evB, 0);
    cudaStreamWaitEvent(sB, evA, 0);

    // Interleaved sim/softmax slices across the two streams.
    for (int i = 0; i < NSLICES; ++i) {
        cudaStream_t s = (i & 1) ? sB : (cudaStream_t)0;
        sim_mma<<<dim3(1, NCONCEPT / 256), 512, SMEM_SIM, s>>>(pAh, pBh, pS, i);
        softmax_row<<<BATCH / NSLICES, 512, 0, s>>>(pS, act, bidx, i * 128);
    }

    // Join sB back into the default stream.
    cudaEventRecord(evJoin, sB);
    cudaStreamWaitEvent(0, evJoin, 0);
}